// round 13
// baseline (speedup 1.0000x reference)
#include <cuda_runtime.h>
#include <cuda_bf16.h>
#include <cstdint>
#include <math.h>

#define B_    8
#define L_    512
#define D_    1024
#define H_    16
#define F_    4096
#define NL_   6
#define ROWS_ (B_*L_)          /* 4096 */
#define NST_  (ROWS_*D_)       /* 4194304 */

typedef __nv_bfloat16 bf16;

// ---------------- scratch (device globals; no allocation allowed) ------------
__device__ float g_state[NST_];
__device__ float g_prev [NST_];
__device__ float g_att  [(size_t)B_*H_*L_*L_];

__device__ bf16 g_xnh[NST_],  g_xnl[NST_];
__device__ bf16 g_qkvh[(size_t)ROWS_*3*D_], g_qkvl[(size_t)ROWS_*3*D_];
__device__ bf16 g_vth[NST_],  g_vtl[NST_];
__device__ bf16 g_ctxh[NST_], g_ctxl[NST_];
__device__ bf16 g_wh[(size_t)B_*H_*L_*L_], g_wl[(size_t)B_*H_*L_*L_];
__device__ bf16 g_hh[(size_t)ROWS_*F_], g_hl[(size_t)ROWS_*F_];

// transposed+split weights [N][K]
__device__ bf16 g_Wqkvh[3*D_*D_], g_Wqkvl[3*D_*D_];
__device__ bf16 g_Woh[D_*D_], g_Wol[D_*D_];
__device__ bf16 g_K1h[(size_t)F_*3*D_], g_K1l[(size_t)F_*3*D_];
__device__ bf16 g_K2h[(size_t)D_*3*F_], g_K2l[(size_t)D_*3*F_];

__device__ float g_hp [ROWS_];
__device__ float g_rem[ROWS_];
__device__ float g_nup[ROWS_];
__device__ float g_uw [ROWS_];

// ---------------- PTX helpers -------------------------------------------------
__device__ __forceinline__ uint32_t smem_u32(const void* p) {
    uint32_t a;
    asm("{ .reg .u64 t; cvta.to.shared.u64 t, %1; cvt.u32.u64 %0, t; }" : "=r"(a) : "l"(p));
    return a;
}
__device__ __forceinline__ void cpa16(uint32_t dst, const void* src, int sz) {
    asm volatile("cp.async.cg.shared.global [%0], [%1], 16, %2;" :: "r"(dst), "l"(src), "r"(sz));
}
__device__ __forceinline__ void ldm4(uint32_t* r, uint32_t addr) {
    asm volatile("ldmatrix.sync.aligned.m8n8.x4.shared.b16 {%0,%1,%2,%3}, [%4];"
        : "=r"(r[0]), "=r"(r[1]), "=r"(r[2]), "=r"(r[3]) : "r"(addr));
}
__device__ __forceinline__ void mma16816(float* c, const uint32_t* a, uint32_t b0, uint32_t b1) {
    asm volatile("mma.sync.aligned.m16n8k16.row.col.f32.bf16.bf16.f32 "
        "{%0,%1,%2,%3}, {%4,%5,%6,%7}, {%8,%9}, {%0,%1,%2,%3};"
        : "+f"(c[0]), "+f"(c[1]), "+f"(c[2]), "+f"(c[3])
        : "r"(a[0]), "r"(a[1]), "r"(a[2]), "r"(a[3]), "r"(b0), "r"(b1));
}
__device__ __forceinline__ void split2(float v0, float v1, bf16* hi, bf16* lo, size_t o) {
    bf16 h0 = __float2bfloat16(v0), h1 = __float2bfloat16(v1);
    __nv_bfloat162 hh2; hh2.x = h0; hh2.y = h1;
    *(__nv_bfloat162*)(hi + o) = hh2;
    __nv_bfloat162 ll2;
    ll2.x = __float2bfloat16(v0 - __bfloat162float(h0));
    ll2.y = __float2bfloat16(v1 - __bfloat162float(h1));
    *(__nv_bfloat162*)(lo + o) = ll2;
}

// ---------------- weight transpose + bf16 split ------------------------------
__device__ __forceinline__ void tsplit_body(const float* __restrict__ in, int inRowLen,
                                            bf16* __restrict__ ohi, bf16* __restrict__ olo,
                                            int outStride, int n0, int k0)
{
    __shared__ float t[32][33];
    int tx = threadIdx.x, ty = threadIdx.y;
    #pragma unroll
    for (int i = 0; i < 32; i += 8)
        t[ty + i][tx] = in[(size_t)(k0 + ty + i) * inRowLen + n0 + tx];
    __syncthreads();
    #pragma unroll
    for (int i = 0; i < 32; i += 8) {
        float v = t[tx][ty + i];
        bf16 h = __float2bfloat16(v);
        size_t o = (size_t)(n0 + ty + i) * outStride + k0 + tx;
        ohi[o] = h;
        olo[o] = __float2bfloat16(v - __bfloat162float(h));
    }
}

// square weights: z = 0..3 -> Wq, Wk, Wv (into packed QKV), Wo
__global__ void prep_square(const float* __restrict__ Wq, const float* __restrict__ Wk,
                            const float* __restrict__ Wv, const float* __restrict__ Wo,
                            bf16* __restrict__ Wqkvh, bf16* __restrict__ Wqkvl,
                            bf16* __restrict__ Woh, bf16* __restrict__ Wol)
{
    int z = blockIdx.z;
    const float* in = (z == 0) ? Wq : (z == 1) ? Wk : (z == 2) ? Wv : Wo;
    bf16* oh = (z == 3) ? Woh : (Wqkvh + (size_t)z * 1024 * 1024);
    bf16* ol = (z == 3) ? Wol : (Wqkvl + (size_t)z * 1024 * 1024);
    tsplit_body(in, 1024, oh, ol, 1024, blockIdx.x * 32, blockIdx.y * 32);
}

// conv weights, flattened 1-D grid: ids [0,12288) = K1, [12288,24576) = K2
__global__ void prep_conv(const float* __restrict__ K1, const float* __restrict__ K2,
                          bf16* __restrict__ K1h, bf16* __restrict__ K1l,
                          bf16* __restrict__ K2h, bf16* __restrict__ K2l)
{
    int id = blockIdx.x;
    if (id < 12288) {
        int w = id / 4096, r = id % 4096;
        int n0 = (r % 128) * 32, k0 = (r / 128) * 32;
        tsplit_body(K1 + (size_t)w * 1024 * 4096, 4096,
                    K1h + (size_t)w * 1024, K1l + (size_t)w * 1024, 3072, n0, k0);
    } else {
        id -= 12288;
        int w = id / 4096, r = id % 4096;
        int n0 = (r % 32) * 32, k0 = (r / 32) * 32;
        tsplit_body(K2 + (size_t)w * 4096 * 1024, 1024,
                    K2h + (size_t)w * 4096, K2l + (size_t)w * 4096, 12288, n0, k0);
    }
}

// per-batch bf16 transpose of the V part of packed qkv
__global__ void transpose_v(const bf16* __restrict__ inh, const bf16* __restrict__ inl,
                            bf16* __restrict__ outh, bf16* __restrict__ outl)
{
    __shared__ bf16 t[32][33];
    int b = blockIdx.z >> 1, sel = blockIdx.z & 1;
    const bf16* in = sel ? inl : inh;
    bf16* out = sel ? outl : outh;
    int c0 = blockIdx.x * 32, l0 = blockIdx.y * 32;
    int tx = threadIdx.x, ty = threadIdx.y;
    #pragma unroll
    for (int i = 0; i < 32; i += 8)
        t[ty + i][tx] = in[((size_t)(b * 512 + l0 + ty + i)) * 3072 + 2048 + c0 + tx];
    __syncthreads();
    #pragma unroll
    for (int i = 0; i < 32; i += 8)
        out[((size_t)(b * 1024 + c0 + ty + i)) * 512 + l0 + tx] = t[tx][ty + i];
}

// ---------------- mma.sync GEMM (128x128 tile, 4-stage pipeline) --------------
// EPI 1: Cf = acc+res (Wo)
// EPI 2: split(relu(acc+bias)) (conv1)
// EPI 5: Cf = acc+bias+res; prev = Cf*uw + prev*(1-uw)  (conv2 + prev_update)
// EPI 6: split(acc * (col<1024 ? 0.125 : 1))  (fused QKV)
#define TSTR    40
#define TBYTES  (128*TSTR*2)       /* 10240 */
#define STAGE_B (4*TBYTES)         /* 40960 */
#define NSTG    4
#define SMEM_SZ (NSTG*STAGE_B)     /* 163840 */

__device__ __forceinline__ void ld_plain(const bf16* __restrict__ src, int row0, int K,
                                         int k0, uint32_t sbase, int tid)
{
    #pragma unroll
    for (int i = 0; i < 2; i++) {
        int unit = i * 256 + tid;
        int row = unit >> 2, ch = unit & 3;
        cpa16(sbase + row * (TSTR*2) + ch * 16,
              src + (size_t)(row0 + row) * K + k0 + ch * 8, 16);
    }
}

template<int DSHIFT>
__device__ __forceinline__ void ld_conv(const bf16* __restrict__ src, int bm,
                                        int k0, uint32_t sbase, int tid)
{
    int w  = k0 >> DSHIFT;
    int cb = k0 & ((1 << DSHIFT) - 1);
    #pragma unroll
    for (int i = 0; i < 2; i++) {
        int unit = i * 256 + tid;
        int row = unit >> 2, ch = unit & 3;
        int r = bm + row;
        int b = r >> 9;
        int l = (r & 511) + w - 1;
        int ok = ((unsigned)l < 512u);
        int lc = ok ? l : 0;
        cpa16(sbase + row * (TSTR*2) + ch * 16,
              src + (((size_t)(b * 512 + lc)) << DSHIFT) + cb + ch * 8, ok ? 16 : 0);
    }
}

template<int CONV, int DSHIFT>
__device__ __forceinline__ void ld_stage(const bf16* __restrict__ Ahi, const bf16* __restrict__ Alo,
                                         const bf16* __restrict__ Bhi, const bf16* __restrict__ Blo,
                                         int bm, int bn, int K, int k0, uint32_t s, int tid)
{
    if (CONV) { ld_conv<DSHIFT>(Ahi, bm, k0, s, tid); ld_conv<DSHIFT>(Alo, bm, k0, s + TBYTES, tid); }
    else      { ld_plain(Ahi, bm, K, k0, s, tid);      ld_plain(Alo, bm, K, k0, s + TBYTES, tid); }
    ld_plain(Bhi, bn, K, k0, s + 2*TBYTES, tid);
    ld_plain(Blo, bn, K, k0, s + 3*TBYTES, tid);
}

template<int CONV, int DSHIFT, int EPI>
__global__ __launch_bounds__(256, 1)
void mm_gemm(const bf16* __restrict__ Ahi, const bf16* __restrict__ Alo,
             const bf16* __restrict__ Bhi, const bf16* __restrict__ Blo,
             float* __restrict__ Cf, bf16* __restrict__ Chi, bf16* __restrict__ Clo,
             const float* __restrict__ res, const float* __restrict__ bias,
             const float* __restrict__ uw, float* __restrict__ prevp,
             int Nglob, int K)
{
    extern __shared__ char smem[];
    uint32_t sb = smem_u32(smem);
    int tid = threadIdx.x, wid = tid >> 5, lane = tid & 31;
    int bm = blockIdx.y * 128, bn = blockIdx.x * 128;
    int wm = wid & 3, wn = wid >> 2;

    float acc[2][8][4];
    #pragma unroll
    for (int mt = 0; mt < 2; mt++)
        #pragma unroll
        for (int nt = 0; nt < 8; nt++)
            #pragma unroll
            for (int j = 0; j < 4; j++) acc[mt][nt][j] = 0.f;

    int nch = K >> 5;   // always >= 32 here

    // prologue: prefetch chunks 0..2 into stages 0..2 (one commit each)
    #pragma unroll
    for (int p = 0; p < 3; p++) {
        ld_stage<CONV,DSHIFT>(Ahi, Alo, Bhi, Blo, bm, bn, K, p << 5, sb + p * STAGE_B, tid);
        asm volatile("cp.async.commit_group;");
    }

    // mainloop: always exactly 3 groups outstanding (tail groups are empty),
    // so wait_group 2 at iter i guarantees chunk i has landed.
    for (int i = 0; i < nch; i++) {
        asm volatile("cp.async.wait_group 2;");
        __syncthreads();
        if (i + 3 < nch) {
            ld_stage<CONV,DSHIFT>(Ahi, Alo, Bhi, Blo, bm, bn, K, (i + 3) << 5,
                                  sb + ((i + 3) & (NSTG - 1)) * STAGE_B, tid);
        }
        asm volatile("cp.async.commit_group;");

        uint32_t s = sb + (i & (NSTG - 1)) * STAGE_B;
        #pragma unroll
        for (int ks = 0; ks < 2; ks++) {
            uint32_t ah[2][4], al[2][4];
            #pragma unroll
            for (int mt = 0; mt < 2; mt++) {
                uint32_t ra = s + (uint32_t)((wm*32 + mt*16) + (lane & 15)) * (TSTR*2)
                            + ks * 32 + (lane >> 4) * 16;
                ldm4(ah[mt], ra);
                ldm4(al[mt], ra + TBYTES);
            }
            uint32_t bh[4][4], bl[4][4];
            #pragma unroll
            for (int g = 0; g < 4; g++) {
                uint32_t rb = s + 2*TBYTES + (uint32_t)((wn*64 + g*16) + (lane & 15)) * (TSTR*2)
                            + ks * 32 + (lane >> 4) * 16;
                ldm4(bh[g], rb);
                ldm4(bl[g], rb + TBYTES);
            }
            #pragma unroll
            for (int mt = 0; mt < 2; mt++)
                #pragma unroll
                for (int nt = 0; nt < 8; nt++) {
                    int g = nt >> 1, o = nt & 1;
                    mma16816(acc[mt][nt], ah[mt], bh[g][o], bh[g][o + 2]);
                    mma16816(acc[mt][nt], ah[mt], bl[g][o], bl[g][o + 2]);
                    mma16816(acc[mt][nt], al[mt], bh[g][o], bh[g][o + 2]);
                }
        }
    }

    #pragma unroll
    for (int mt = 0; mt < 2; mt++)
        #pragma unroll
        for (int nt = 0; nt < 8; nt++)
            #pragma unroll
            for (int half = 0; half < 2; half++) {
                int row = bm + wm*32 + mt*16 + (lane >> 2) + half*8;
                int col = bn + wn*64 + nt*8 + (lane & 3)*2;
                float v0 = acc[mt][nt][half*2 + 0];
                float v1 = acc[mt][nt][half*2 + 1];
                size_t o = (size_t)row * Nglob + col;
                if (EPI == 1) {
                    float2 rr = *(const float2*)(res + o);
                    *(float2*)(Cf + o) = make_float2(v0 + rr.x, v1 + rr.y);
                } else if (EPI == 2) {
                    float2 bb = *(const float2*)(bias + col);
                    v0 = fmaxf(v0 + bb.x, 0.f);
                    v1 = fmaxf(v1 + bb.y, 0.f);
                    split2(v0, v1, Chi, Clo, o);
                } else if (EPI == 5) {
                    float2 rr = *(const float2*)(res + o);
                    float2 bb = *(const float2*)(bias + col);
                    float s0 = v0 + bb.x + rr.x;
                    float s1 = v1 + bb.y + rr.y;
                    *(float2*)(Cf + o) = make_float2(s0, s1);
                    float u = uw[row];
                    float2 pv = *(const float2*)(prevp + o);
                    *(float2*)(prevp + o) = make_float2(s0 * u + pv.x * (1.f - u),
                                                        s1 * u + pv.y * (1.f - u));
                } else {  // EPI 6: fused QKV split, q-scale on first 1024 cols
                    float a = (col < 1024) ? 0.125f : 1.0f;
                    split2(v0 * a, v1 * a, Chi, Clo, o);
                }
            }
}

// ---------------- attention: logits = q@k^T (per bh), K=64 --------------------
#define QSTR 72
#define QTB  (128*QSTR*2)   /* 18432 */
#define QSMEM (4*QTB)       /* 73728 */

__global__ __launch_bounds__(256, 2)
void attn_qk(const bf16* __restrict__ qkvh, const bf16* __restrict__ qkvl,
             float* __restrict__ att)
{
    extern __shared__ char smem[];
    uint32_t sb = smem_u32(smem);
    int tid = threadIdx.x, wid = tid >> 5, lane = tid & 31;
    int bz = blockIdx.z;
    int b = bz >> 4, h = bz & 15;
    size_t qbase = ((size_t)(b*512 + blockIdx.y*128)) * 3072 + h*64;
    size_t kbase = ((size_t)(b*512 + blockIdx.x*128)) * 3072 + 1024 + h*64;

    #pragma unroll
    for (int i = 0; i < 4; i++) {
        int unit = i * 256 + tid;
        int row = unit >> 3, ch = unit & 7;
        uint32_t d = (uint32_t)(row * (QSTR*2) + ch * 16);
        size_t so = (size_t)row * 3072 + ch * 8;
        cpa16(sb + d,         qkvh + qbase + so, 16);
        cpa16(sb + QTB + d,   qkvl + qbase + so, 16);
        cpa16(sb + 2*QTB + d, qkvh + kbase + so, 16);
        cpa16(sb + 3*QTB + d, qkvl + kbase + so, 16);
    }
    asm volatile("cp.async.commit_group;");
    asm volatile("cp.async.wait_group 0;");
    __syncthreads();

    int wm = wid & 3, wn = wid >> 2;
    float acc[2][8][4];
    #pragma unroll
    for (int mt = 0; mt < 2; mt++)
        #pragma unroll
        for (int nt = 0; nt < 8; nt++)
            #pragma unroll
            for (int j = 0; j < 4; j++) acc[mt][nt][j] = 0.f;

    #pragma unroll
    for (int ks = 0; ks < 4; ks++) {
        uint32_t ah[2][4], al[2][4];
        #pragma unroll
        for (int mt = 0; mt < 2; mt++) {
            uint32_t ra = sb + (uint32_t)((wm*32 + mt*16) + (lane & 15)) * (QSTR*2)
                        + ks * 32 + (lane >> 4) * 16;
            ldm4(ah[mt], ra);
            ldm4(al[mt], ra + QTB);
        }
        uint32_t bh[4][4], bl[4][4];
        #pragma unroll
        for (int g = 0; g < 4; g++) {
            uint32_t rb = sb + 2*QTB + (uint32_t)((wn*64 + g*16) + (lane & 15)) * (QSTR*2)
                        + ks * 32 + (lane >> 4) * 16;
            ldm4(bh[g], rb);
            ldm4(bl[g], rb + QTB);
        }
        #pragma unroll
        for (int mt = 0; mt < 2; mt++)
            #pragma unroll
            for (int nt = 0; nt < 8; nt++) {
                int g = nt >> 1, o = nt & 1;
                mma16816(acc[mt][nt], ah[mt], bh[g][o], bh[g][o + 2]);
                mma16816(acc[mt][nt], ah[mt], bl[g][o], bl[g][o + 2]);
                mma16816(acc[mt][nt], al[mt], bh[g][o], bh[g][o + 2]);
            }
    }

    #pragma unroll
    for (int mt = 0; mt < 2; mt++)
        #pragma unroll
        for (int nt = 0; nt < 8; nt++)
            #pragma unroll
            for (int half = 0; half < 2; half++) {
                int rloc = wm*32 + mt*16 + (lane >> 2) + half*8;
                int cloc = wn*64 + nt*8 + (lane & 3)*2;
                float* ap = att + ((size_t)bz*512 + blockIdx.y*128 + rloc)*512
                          + blockIdx.x*128 + cloc;
                *(float2*)ap = make_float2(acc[mt][nt][half*2], acc[mt][nt][half*2 + 1]);
            }
}

// ---------------- attention: ctx = w@v (per bh), tile 128x64, K=512 -----------
#define WA_B  (128*TSTR*2)   /* 10240 */
#define WB_B  (64*TSTR*2)    /* 5120 */
#define WSTAGE (2*WA_B + 2*WB_B)   /* 30720 */
#define WSMEM (2*WSTAGE)           /* 61440 */

__global__ __launch_bounds__(256, 2)
void attn_wv(const bf16* __restrict__ wh, const bf16* __restrict__ wl,
             const bf16* __restrict__ vth, const bf16* __restrict__ vtl,
             bf16* __restrict__ ctxh, bf16* __restrict__ ctxl)
{
    extern __shared__ char smem[];
    uint32_t sb = smem_u32(smem);
    int tid = threadIdx.x, wid = tid >> 5, lane = tid & 31;
    int bz = blockIdx.y;
    int b = bz >> 4, h = bz & 15;
    size_t abase = (size_t)bz*262144 + (size_t)blockIdx.x*65536;
    size_t bbase = (size_t)bz*32768;
    int wm = wid & 3, wn = wid >> 2;

    float acc[2][4][4];
    #pragma unroll
    for (int mt = 0; mt < 2; mt++)
        #pragma unroll
        for (int nt = 0; nt < 4; nt++)
            #pragma unroll
            for (int j = 0; j < 4; j++) acc[mt][nt][j] = 0.f;

    auto load_chunk = [&](int k0, uint32_t s) {
        #pragma unroll
        for (int i = 0; i < 2; i++) {
            int unit = i * 256 + tid;
            int row = unit >> 2, ch = unit & 3;
            uint32_t d = (uint32_t)(row * (TSTR*2) + ch * 16);
            size_t so = abase + (size_t)row * 512 + k0 + ch * 8;
            cpa16(s + d,        wh + so, 16);
            cpa16(s + WA_B + d, wl + so, 16);
        }
        {
            int row = tid >> 2, ch = tid & 3;
            uint32_t d = (uint32_t)(row * (TSTR*2) + ch * 16);
            size_t so = bbase + (size_t)row * 512 + k0 + ch * 8;
            cpa16(s + 2*WA_B + d,        vth + so, 16);
            cpa16(s + 2*WA_B + WB_B + d, vtl + so, 16);
        }
    };

    load_chunk(0, sb);
    asm volatile("cp.async.commit_group;");

    for (int i = 0; i < 16; i++) {
        asm volatile("cp.async.wait_group 0;");
        __syncthreads();
        if (i + 1 < 16) {
            load_chunk((i + 1) << 5, sb + ((i + 1) & 1) * WSTAGE);
            asm volatile("cp.async.commit_group;");
        }

        uint32_t s = sb + (i & 1) * WSTAGE;
        #pragma unroll
        for (int ks = 0; ks < 2; ks++) {
            uint32_t ah[2][4], al[2][4];
            #pragma unroll
            for (int mt = 0; mt < 2; mt++) {
                uint32_t ra = s + (uint32_t)((wm*32 + mt*16) + (lane & 15)) * (TSTR*2)
                            + ks * 32 + (lane >> 4) * 16;
                ldm4(ah[mt], ra);
                ldm4(al[mt], ra + WA_B);
            }
            uint32_t bh[2][4], bl[2][4];
            #pragma unroll
            for (int g = 0; g < 2; g++) {
                uint32_t rb = s + 2*WA_B + (uint32_t)((wn*32 + g*16) + (lane & 15)) * (TSTR*2)
                            + ks * 32 + (lane >> 4) * 16;
                ldm4(bh[g], rb);
                ldm4(bl[g], rb + WB_B);
            }
            #pragma unroll
            for (int mt = 0; mt < 2; mt++)
                #pragma unroll
                for (int nt = 0; nt < 4; nt++) {
                    int g = nt >> 1, o = nt & 1;
                    mma16816(acc[mt][nt], ah[mt], bh[g][o], bh[g][o + 2]);
                    mma16816(acc[mt][nt], ah[mt], bl[g][o], bl[g][o + 2]);
                    mma16816(acc[mt][nt], al[mt], bh[g][o], bh[g][o + 2]);
                }
        }
    }

    #pragma unroll
    for (int mt = 0; mt < 2; mt++)
        #pragma unroll
        for (int nt = 0; nt < 4; nt++)
            #pragma unroll
            for (int half = 0; half < 2; half++) {
                int rloc = wm*32 + mt*16 + (lane >> 2) + half*8;
                int row = b*512 + blockIdx.x*128 + rloc;
                int col = h*64 + wn*32 + nt*8 + (lane & 3)*2;
                size_t o = (size_t)row * 1024 + col;
                split2(acc[mt][nt][half*2], acc[mt][nt][half*2 + 1], ctxh, ctxl, o);
            }
}

// ---------------- softmax + bf16 split ----------------------------------------
__global__ void softmax_split(const float* __restrict__ att,
                              bf16* __restrict__ wh, bf16* __restrict__ wl)
{
    int row  = blockIdx.x * 8 + (threadIdx.x >> 5);
    int lane = threadIdx.x & 31;
    const float* x = att + (size_t)row * 512;
    float v[16];
    float m = -1e30f;
    #pragma unroll
    for (int i = 0; i < 16; i++) { v[i] = x[lane + 32*i]; m = fmaxf(m, v[i]); }
    #pragma unroll
    for (int o = 16; o; o >>= 1) m = fmaxf(m, __shfl_xor_sync(0xffffffffu, m, o));
    float s = 0.f;
    #pragma unroll
    for (int i = 0; i < 16; i++) { v[i] = expf(v[i] - m); s += v[i]; }
    #pragma unroll
    for (int o = 16; o; o >>= 1) s += __shfl_xor_sync(0xffffffffu, s, o);
    float inv = 1.f / s;
    #pragma unroll
    for (int i = 0; i < 16; i++) {
        float w = v[i] * inv;
        bf16 hh = __float2bfloat16(w);
        size_t o = (size_t)row * 512 + lane + 32*i;
        wh[o] = hh;
        wl[o] = __float2bfloat16(w - __bfloat162float(hh));
    }
}

// ---------------- fused: time/pos add + ACT halt + layernorm1 -----------------
__global__ __launch_bounds__(256) void pre_layer(
    int t, const float* __restrict__ p_w, const float* __restrict__ p_b,
    const float* __restrict__ g, const float* __restrict__ bgm)
{
    __shared__ float sh1[8], sh2[8], sh3[8];
    const float NEG_LOG_INC = -0.018024149455921103f;
    int row = blockIdx.x;
    int l   = row & 511;
    int tid = threadIdx.x;
    float* x = g_state + (size_t)row * 1024;
    float v[4];
    float sum = 0.f, dot = 0.f;
    #pragma unroll
    for (int j = 0; j < 4; j++) {
        int d = tid + 256*j;
        int i = d & 511;
        float invt = expf((float)i * NEG_LOG_INC);
        float a1 = (float)l * invt;
        float a2 = (float)t * invt;
        float sig = (d < 512) ? (sinf(a1) + sinf(a2)) : (cosf(a1) + cosf(a2));
        float val = x[d] + sig;
        x[d] = val;
        v[j] = val;
        sum += val;
        dot += val * p_w[d];
    }
    #pragma unroll
    for (int o = 16; o; o >>= 1) {
        sum += __shfl_xor_sync(0xffffffffu, sum, o);
        dot += __shfl_xor_sync(0xffffffffu, dot, o);
    }
    if ((tid & 31) == 0) { sh1[tid >> 5] = sum; sh3[tid >> 5] = dot; }
    __syncthreads();
    float tot = 0.f, dtot = 0.f;
    #pragma unroll
    for (int w = 0; w < 8; w++) { tot += sh1[w]; dtot += sh3[w]; }
    float mu = tot * (1.f / 1024.f);
    float q = 0.f;
    #pragma unroll
    for (int j = 0; j < 4; j++) { float d = v[j] - mu; q += d * d; }
    #pragma unroll
    for (int o = 16; o; o >>= 1) q += __shfl_xor_sync(0xffffffffu, q, o);
    if ((tid & 31) == 0) sh2[tid >> 5] = q;
    __syncthreads();

    if (tid == 0) {
        float p   = 1.f / (1.f + expf(-(dtot + p_b[0])));
        float hp  = g_hp[row], rem = g_rem[row], nup = g_nup[row];
        float still = (hp < 1.0f) ? 1.f : 0.f;
        float add   = hp + p * still;
        float nh    = ((add > 0.9f) ? 1.f : 0.f) * still;
        still       = ((add <= 0.9f) ? 1.f : 0.f) * still;
        hp  += p * still;
        rem += nh * (1.f - hp);
        hp  += nh * rem;
        nup += still + nh;
        g_hp[row] = hp; g_rem[row] = rem; g_nup[row] = nup;
        g_uw[row] = p * still + nh * rem;
    }

    float qt = 0.f;
    #pragma unroll
    for (int w = 0; w < 8; w++) qt += sh2[w];
    float sd  = sqrtf(qt / 1023.f);
    float inv = 1.f / (sd + 1e-6f);
    #pragma unroll
    for (int j = 0; j < 4; j++) {
        int d = tid + 256*j;
        float y = g[d] * (v[j] - mu) * inv + bgm[d];
        bf16 h = __float2bfloat16(y);
        size_t o = (size_t)row * 1024 + d;
        g_xnh[o] = h;
        g_xnl[o] = __float2bfloat16(y - __bfloat162float(h));
    }
}

// ---------------- misc elementwise --------------------------------------------
__global__ void embed_init(const int* __restrict__ X, const float* __restrict__ emb) {
    int idx = blockIdx.x * 256 + threadIdx.x;
    int row = idx >> 10;
    int d   = idx & 1023;
    g_state[idx] = emb[(size_t)X[row] * 1024 + d];
    g_prev[idx]  = 0.f;
}

__global__ void zero_act() {
    int i = blockIdx.x * 256 + threadIdx.x;
    if (i < ROWS_) { g_hp[i] = 0.f; g_rem[i] = 0.f; g_nup[i] = 0.f; }
}

// layernorm (fp32 in) -> bf16 hi/lo split outputs  (ln2)
__global__ __launch_bounds__(256) void layernorm_k(
    const float* __restrict__ in, bf16* __restrict__ ohi, bf16* __restrict__ olo,
    const float* __restrict__ g, const float* __restrict__ b)
{
    __shared__ float sh1[8], sh2[8];
    int row = blockIdx.x;
    int tid = threadIdx.x;
    const float* x = in + (size_t)row * 1024;
    float v[4];
    #pragma unroll
    for (int j = 0; j < 4; j++) v[j] = x[tid + 256*j];
    float s = v[0] + v[1] + v[2] + v[3];
    #pragma unroll
    for (int o = 16; o; o >>= 1) s += __shfl_xor_sync(0xffffffffu, s, o);
    if ((tid & 31) == 0) sh1[tid >> 5] = s;
    __syncthreads();
    float tot = 0.f;
    #pragma unroll
    for (int w = 0; w < 8; w++) tot += sh1[w];
    float mu = tot * (1.f / 1024.f);
    float q = 0.f;
    #pragma unroll
    for (int j = 0; j < 4; j++) { float d = v[j] - mu; q += d * d; }
    #pragma unroll
    for (int o = 16; o; o >>= 1) q += __shfl_xor_sync(0xffffffffu, q, o);
    if ((tid & 31) == 0) sh2[tid >> 5] = q;
    __syncthreads();
    float qt = 0.f;
    #pragma unroll
    for (int w = 0; w < 8; w++) qt += sh2[w];
    float sd  = sqrtf(qt / 1023.f);
    float inv = 1.f / (sd + 1e-6f);
    #pragma unroll
    for (int j = 0; j < 4; j++) {
        int d = tid + 256*j;
        float y = g[d] * (v[j] - mu) * inv + b[d];
        bf16 h = __float2bfloat16(y);
        size_t o = (size_t)row * 1024 + d;
        ohi[o] = h;
        olo[o] = __float2bfloat16(y - __bfloat162float(h));
    }
}

// ---------------- head --------------------------------------------------------
__global__ __launch_bounds__(256) void head_out(
    const float* __restrict__ W_out, const float* __restrict__ b_out, float* __restrict__ out)
{
    __shared__ float sh[4][256];
    int b = blockIdx.x;
    int tid = threadIdx.x;
    float sum[4] = {0.f, 0.f, 0.f, 0.f};
    for (int l = 0; l < 512; l++) {
        const float* p = g_prev + ((size_t)(b*512 + l)) * 1024;
        #pragma unroll
        for (int j = 0; j < 4; j++) sum[j] += p[tid + 256*j];
    }
    float part[4] = {0.f, 0.f, 0.f, 0.f};
    #pragma unroll
    for (int j = 0; j < 4; j++) {
        int d = tid + 256*j;
        float m = sum[j] * (1.f / 512.f);
        #pragma unroll
        for (int o = 0; o < 4; o++) part[o] += m * W_out[d*4 + o];
    }
    #pragma unroll
    for (int o = 0; o < 4; o++) sh[o][tid] = part[o];
    __syncthreads();
    for (int s = 128; s > 0; s >>= 1) {
        if (tid < s)
            #pragma unroll
            for (int o = 0; o < 4; o++) sh[o][tid] += sh[o][tid + s];
        __syncthreads();
    }
    if (tid == 0) {
        float a[4];
        #pragma unroll
        for (int o = 0; o < 4; o++) { a[o] = sh[o][0] + b_out[o]; out[b*4 + o] = a[o]; }
        float mx = fmaxf(fmaxf(a[0], a[1]), fmaxf(a[2], a[3]));
        float e[4], s = 0.f;
        #pragma unroll
        for (int o = 0; o < 4; o++) { e[o] = expf(a[o] - mx); s += e[o]; }
        #pragma unroll
        for (int o = 0; o < 4; o++) out[32 + b*4 + o] = e[o] / s;
    }
}

__global__ void tail_out(float* __restrict__ out) {
    int i = blockIdx.x * 256 + threadIdx.x;
    out[64 + i]        = g_rem[i];
    out[64 + 4096 + i] = g_nup[i];
}

// ---------------- launcher ----------------------------------------------------
extern "C" void kernel_launch(void* const* d_in, const int* in_sizes, int n_in,
                              void* d_out, int out_size) {
    const int*   X     = (const int*)  d_in[0];
    const float* emb   = (const float*)d_in[1];
    const float* p_w   = (const float*)d_in[2];
    const float* p_b   = (const float*)d_in[3];
    const float* Wq    = (const float*)d_in[4];
    const float* Wk    = (const float*)d_in[5];
    const float* Wv    = (const float*)d_in[6];
    const float* Wo    = (const float*)d_in[7];
    const float* ln1_g = (const float*)d_in[8];
    const float* ln1_b = (const float*)d_in[9];
    const float* ln2_g = (const float*)d_in[10];
    const float* ln2_b = (const float*)d_in[11];
    const float* K1    = (const float*)d_in[12];
    const float* c1_b  = (const float*)d_in[13];
    const float* K2    = (const float*)d_in[14];
    const float* c2_b  = (const float*)d_in[15];
    const float* W_out = (const float*)d_in[16];
    const float* b_out = (const float*)d_in[17];
    float* out = (float*)d_out;

    float *state, *att, *prevp, *uw;
    bf16 *xnh, *xnl, *qkvh, *qkvl, *vth, *vtl, *ctxh, *ctxl, *wh, *wl, *hh, *hl;
    bf16 *Wqkvh, *Wqkvl, *Woh, *Wol, *K1h, *K1l, *K2h, *K2l;
    cudaGetSymbolAddress((void**)&state, g_state);
    cudaGetSymbolAddress((void**)&prevp, g_prev);
    cudaGetSymbolAddress((void**)&uw,    g_uw);
    cudaGetSymbolAddress((void**)&att,   g_att);
    cudaGetSymbolAddress((void**)&xnh,   g_xnh);   cudaGetSymbolAddress((void**)&xnl,  g_xnl);
    cudaGetSymbolAddress((void**)&qkvh,  g_qkvh);  cudaGetSymbolAddress((void**)&qkvl, g_qkvl);
    cudaGetSymbolAddress((void**)&vth,   g_vth);   cudaGetSymbolAddress((void**)&vtl,  g_vtl);
    cudaGetSymbolAddress((void**)&ctxh,  g_ctxh);  cudaGetSymbolAddress((void**)&ctxl, g_ctxl);
    cudaGetSymbolAddress((void**)&wh,    g_wh);    cudaGetSymbolAddress((void**)&wl,   g_wl);
    cudaGetSymbolAddress((void**)&hh,    g_hh);    cudaGetSymbolAddress((void**)&hl,   g_hl);
    cudaGetSymbolAddress((void**)&Wqkvh, g_Wqkvh); cudaGetSymbolAddress((void**)&Wqkvl,g_Wqkvl);
    cudaGetSymbolAddress((void**)&Woh,   g_Woh);   cudaGetSymbolAddress((void**)&Wol,  g_Wol);
    cudaGetSymbolAddress((void**)&K1h,   g_K1h);   cudaGetSymbolAddress((void**)&K1l,  g_K1l);
    cudaGetSymbolAddress((void**)&K2h,   g_K2h);   cudaGetSymbolAddress((void**)&K2l,  g_K2l);

    cudaFuncSetAttribute(mm_gemm<0,0,1>,  cudaFuncAttributeMaxDynamicSharedMemorySize, SMEM_SZ);
    cudaFuncSetAttribute(mm_gemm<0,0,6>,  cudaFuncAttributeMaxDynamicSharedMemorySize, SMEM_SZ);
    cudaFuncSetAttribute(mm_gemm<1,10,2>, cudaFuncAttributeMaxDynamicSharedMemorySize, SMEM_SZ);
    cudaFuncSetAttribute(mm_gemm<1,12,5>, cudaFuncAttributeMaxDynamicSharedMemorySize, SMEM_SZ);
    cudaFuncSetAttribute(attn_qk, cudaFuncAttributeMaxDynamicSharedMemorySize, QSMEM);
    cudaFuncSetAttribute(attn_wv, cudaFuncAttributeMaxDynamicSharedMemorySize, WSMEM);

    dim3 tb(32, 8);
    // launch 1: square weights (Wq/Wk/Wv packed + Wo)
    prep_square<<<dim3(32, 32, 4), tb>>>(Wq, Wk, Wv, Wo, Wqkvh, Wqkvl, Woh, Wol);
    // launch 2: conv weights (K1 + K2), flattened
    prep_conv<<<24576, tb>>>(K1, K2, K1h, K1l, K2h, K2l);
    // launches 3, 4
    embed_init<<<NST_/256, 256>>>(X, emb);
    zero_act<<<16, 256>>>();

    for (int t = 0; t < NL_; t++) {
        // launch 5 (t=0): pre_layer; launch 6: QKV mm_gemm  -> ncu -s 5 -c 1 profiles it
        pre_layer<<<ROWS_, 256>>>(t, p_w, p_b, ln1_g, ln1_b);

        mm_gemm<0,0,6><<<dim3(24, 32), 256, SMEM_SZ>>>(xnh, xnl, Wqkvh, Wqkvl,
            nullptr, qkvh, qkvl, nullptr, nullptr, nullptr, nullptr, 3*D_, D_);

        transpose_v<<<dim3(32, 16, 16), tb>>>(qkvh, qkvl, vth, vtl);

        attn_qk<<<dim3(4, 4, B_*H_), 256, QSMEM>>>(qkvh, qkvl, att);
        softmax_split<<<(B_*H_*L_)/8, 256>>>(att, wh, wl);
        attn_wv<<<dim3(4, B_*H_), 256, WSMEM>>>(wh, wl, vth, vtl, ctxh, ctxl);

        dim3 gp(D_/128, ROWS_/128);
        mm_gemm<0,0,1><<<gp, 256, SMEM_SZ>>>(ctxh, ctxl, Woh, Wol,
            state, nullptr, nullptr, state, nullptr, nullptr, nullptr, D_, D_);
        layernorm_k<<<ROWS_, 256>>>(state, xnh, xnl, ln2_g, ln2_b);

        mm_gemm<1,10,2><<<dim3(F_/128, ROWS_/128), 256, SMEM_SZ>>>(xnh, xnl, K1h, K1l,
            nullptr, hh, hl, nullptr, c1_b, nullptr, nullptr, F_, 3*D_);
        // conv2 + fused prev_update
        mm_gemm<1,12,5><<<gp, 256, SMEM_SZ>>>(hh, hl, K2h, K2l,
            state, nullptr, nullptr, state, c2_b, uw, prevp, D_, 3*F_);
    }

    head_out<<<B_, 256>>>(W_out, b_out, out);
    tail_out<<<ROWS_/256, 256>>>(out);
}

// round 14
// speedup vs baseline: 1.1026x; 1.1026x over previous
#include <cuda_runtime.h>
#include <cuda_bf16.h>
#include <cstdint>
#include <math.h>

#define B_    8
#define L_    512
#define D_    1024
#define H_    16
#define F_    4096
#define NL_   6
#define ROWS_ (B_*L_)          /* 4096 */
#define NST_  (ROWS_*D_)       /* 4194304 */

typedef __nv_bfloat16 bf16;

// ---------------- scratch (device globals; no allocation allowed) ------------
__device__ float g_state[NST_];
__device__ float g_prev [NST_];

__device__ bf16 g_xnh[NST_],  g_xnl[NST_];
__device__ bf16 g_qkvh[(size_t)ROWS_*3*D_], g_qkvl[(size_t)ROWS_*3*D_];
__device__ bf16 g_vth[NST_],  g_vtl[NST_];
__device__ bf16 g_ctxh[NST_], g_ctxl[NST_];
__device__ bf16 g_wh[(size_t)B_*H_*L_*L_], g_wl[(size_t)B_*H_*L_*L_];
__device__ bf16 g_hh[(size_t)ROWS_*F_], g_hl[(size_t)ROWS_*F_];

// transposed+split weights [N][K]
__device__ bf16 g_Wqkvh[3*D_*D_], g_Wqkvl[3*D_*D_];
__device__ bf16 g_Woh[D_*D_], g_Wol[D_*D_];
__device__ bf16 g_K1h[(size_t)F_*3*D_], g_K1l[(size_t)F_*3*D_];
__device__ bf16 g_K2h[(size_t)D_*3*F_], g_K2l[(size_t)D_*3*F_];

__device__ float g_hp [ROWS_];
__device__ float g_rem[ROWS_];
__device__ float g_nup[ROWS_];
__device__ float g_uw [ROWS_];

// ---------------- PTX helpers -------------------------------------------------
__device__ __forceinline__ uint32_t smem_u32(const void* p) {
    uint32_t a;
    asm("{ .reg .u64 t; cvta.to.shared.u64 t, %1; cvt.u32.u64 %0, t; }" : "=r"(a) : "l"(p));
    return a;
}
__device__ __forceinline__ void cpa16(uint32_t dst, const void* src, int sz) {
    asm volatile("cp.async.cg.shared.global [%0], [%1], 16, %2;" :: "r"(dst), "l"(src), "r"(sz));
}
__device__ __forceinline__ void ldm4(uint32_t* r, uint32_t addr) {
    asm volatile("ldmatrix.sync.aligned.m8n8.x4.shared.b16 {%0,%1,%2,%3}, [%4];"
        : "=r"(r[0]), "=r"(r[1]), "=r"(r[2]), "=r"(r[3]) : "r"(addr));
}
__device__ __forceinline__ void mma16816(float* c, const uint32_t* a, uint32_t b0, uint32_t b1) {
    asm volatile("mma.sync.aligned.m16n8k16.row.col.f32.bf16.bf16.f32 "
        "{%0,%1,%2,%3}, {%4,%5,%6,%7}, {%8,%9}, {%0,%1,%2,%3};"
        : "+f"(c[0]), "+f"(c[1]), "+f"(c[2]), "+f"(c[3])
        : "r"(a[0]), "r"(a[1]), "r"(a[2]), "r"(a[3]), "r"(b0), "r"(b1));
}
__device__ __forceinline__ void split2(float v0, float v1, bf16* hi, bf16* lo, size_t o) {
    bf16 h0 = __float2bfloat16(v0), h1 = __float2bfloat16(v1);
    __nv_bfloat162 hh2; hh2.x = h0; hh2.y = h1;
    *(__nv_bfloat162*)(hi + o) = hh2;
    __nv_bfloat162 ll2;
    ll2.x = __float2bfloat16(v0 - __bfloat162float(h0));
    ll2.y = __float2bfloat16(v1 - __bfloat162float(h1));
    *(__nv_bfloat162*)(lo + o) = ll2;
}

// ---------------- weight transpose + bf16 split ------------------------------
__device__ __forceinline__ void tsplit_body(const float* __restrict__ in, int inRowLen,
                                            bf16* __restrict__ ohi, bf16* __restrict__ olo,
                                            int outStride, int n0, int k0)
{
    __shared__ float t[32][33];
    int tx = threadIdx.x, ty = threadIdx.y;
    #pragma unroll
    for (int i = 0; i < 32; i += 8)
        t[ty + i][tx] = in[(size_t)(k0 + ty + i) * inRowLen + n0 + tx];
    __syncthreads();
    #pragma unroll
    for (int i = 0; i < 32; i += 8) {
        float v = t[tx][ty + i];
        bf16 h = __float2bfloat16(v);
        size_t o = (size_t)(n0 + ty + i) * outStride + k0 + tx;
        ohi[o] = h;
        olo[o] = __float2bfloat16(v - __bfloat162float(h));
    }
}

__global__ void prep_square(const float* __restrict__ Wq, const float* __restrict__ Wk,
                            const float* __restrict__ Wv, const float* __restrict__ Wo,
                            bf16* __restrict__ Wqkvh, bf16* __restrict__ Wqkvl,
                            bf16* __restrict__ Woh, bf16* __restrict__ Wol)
{
    int z = blockIdx.z;
    const float* in = (z == 0) ? Wq : (z == 1) ? Wk : (z == 2) ? Wv : Wo;
    bf16* oh = (z == 3) ? Woh : (Wqkvh + (size_t)z * 1024 * 1024);
    bf16* ol = (z == 3) ? Wol : (Wqkvl + (size_t)z * 1024 * 1024);
    tsplit_body(in, 1024, oh, ol, 1024, blockIdx.x * 32, blockIdx.y * 32);
}

__global__ void prep_conv(const float* __restrict__ K1, const float* __restrict__ K2,
                          bf16* __restrict__ K1h, bf16* __restrict__ K1l,
                          bf16* __restrict__ K2h, bf16* __restrict__ K2l)
{
    int id = blockIdx.x;
    if (id < 12288) {
        int w = id / 4096, r = id % 4096;
        int n0 = (r % 128) * 32, k0 = (r / 128) * 32;
        tsplit_body(K1 + (size_t)w * 1024 * 4096, 4096,
                    K1h + (size_t)w * 1024, K1l + (size_t)w * 1024, 3072, n0, k0);
    } else {
        id -= 12288;
        int w = id / 4096, r = id % 4096;
        int n0 = (r % 32) * 32, k0 = (r / 32) * 32;
        tsplit_body(K2 + (size_t)w * 4096 * 1024, 1024,
                    K2h + (size_t)w * 4096, K2l + (size_t)w * 4096, 12288, n0, k0);
    }
}

// per-batch bf16 transpose of the V part of packed qkv
__global__ void transpose_v(const bf16* __restrict__ inh, const bf16* __restrict__ inl,
                            bf16* __restrict__ outh, bf16* __restrict__ outl)
{
    __shared__ bf16 t[32][33];
    int b = blockIdx.z >> 1, sel = blockIdx.z & 1;
    const bf16* in = sel ? inl : inh;
    bf16* out = sel ? outl : outh;
    int c0 = blockIdx.x * 32, l0 = blockIdx.y * 32;
    int tx = threadIdx.x, ty = threadIdx.y;
    #pragma unroll
    for (int i = 0; i < 32; i += 8)
        t[ty + i][tx] = in[((size_t)(b * 512 + l0 + ty + i)) * 3072 + 2048 + c0 + tx];
    __syncthreads();
    #pragma unroll
    for (int i = 0; i < 32; i += 8)
        out[((size_t)(b * 1024 + c0 + ty + i)) * 512 + l0 + tx] = t[tx][ty + i];
}

// ---------------- mma.sync GEMM (128x128 tile, 2-stage, occ 2 — R11 config) ---
// EPI 1: Cf = acc+res (Wo)
// EPI 2: split(relu(acc+bias)) (conv1)
// EPI 5: Cf = acc+bias+res; prev = Cf*uw + prev*(1-uw)  (conv2 + prev_update)
// EPI 6: split(acc * (col<1024 ? 0.125 : 1))  (fused QKV)
#define TSTR    40
#define TBYTES  (128*TSTR*2)       /* 10240 */
#define STAGE_B (4*TBYTES)         /* 40960 */
#define SMEM_SZ (2*STAGE_B)        /* 81920 */

__device__ __forceinline__ void ld_plain(const bf16* __restrict__ src, int row0, int K,
                                         int k0, uint32_t sbase, int tid)
{
    #pragma unroll
    for (int i = 0; i < 2; i++) {
        int unit = i * 256 + tid;
        int row = unit >> 2, ch = unit & 3;
        cpa16(sbase + row * (TSTR*2) + ch * 16,
              src + (size_t)(row0 + row) * K + k0 + ch * 8, 16);
    }
}

template<int DSHIFT>
__device__ __forceinline__ void ld_conv(const bf16* __restrict__ src, int bm,
                                        int k0, uint32_t sbase, int tid)
{
    int w  = k0 >> DSHIFT;
    int cb = k0 & ((1 << DSHIFT) - 1);
    #pragma unroll
    for (int i = 0; i < 2; i++) {
        int unit = i * 256 + tid;
        int row = unit >> 2, ch = unit & 3;
        int r = bm + row;
        int b = r >> 9;
        int l = (r & 511) + w - 1;
        int ok = ((unsigned)l < 512u);
        int lc = ok ? l : 0;
        cpa16(sbase + row * (TSTR*2) + ch * 16,
              src + (((size_t)(b * 512 + lc)) << DSHIFT) + cb + ch * 8, ok ? 16 : 0);
    }
}

template<int CONV, int DSHIFT>
__device__ __forceinline__ void ld_stage(const bf16* __restrict__ Ahi, const bf16* __restrict__ Alo,
                                         const bf16* __restrict__ Bhi, const bf16* __restrict__ Blo,
                                         int bm, int bn, int K, int k0, uint32_t s, int tid)
{
    if (CONV) { ld_conv<DSHIFT>(Ahi, bm, k0, s, tid); ld_conv<DSHIFT>(Alo, bm, k0, s + TBYTES, tid); }
    else      { ld_plain(Ahi, bm, K, k0, s, tid);      ld_plain(Alo, bm, K, k0, s + TBYTES, tid); }
    ld_plain(Bhi, bn, K, k0, s + 2*TBYTES, tid);
    ld_plain(Blo, bn, K, k0, s + 3*TBYTES, tid);
}

template<int CONV, int DSHIFT, int EPI>
__global__ __launch_bounds__(256, 2)
void mm_gemm(const bf16* __restrict__ Ahi, const bf16* __restrict__ Alo,
             const bf16* __restrict__ Bhi, const bf16* __restrict__ Blo,
             float* __restrict__ Cf, bf16* __restrict__ Chi, bf16* __restrict__ Clo,
             const float* __restrict__ res, const float* __restrict__ bias,
             const float* __restrict__ uw, float* __restrict__ prevp,
             int Nglob, int K)
{
    extern __shared__ char smem[];
    uint32_t sb = smem_u32(smem);
    int tid = threadIdx.x, wid = tid >> 5, lane = tid & 31;
    int bm = blockIdx.y * 128, bn = blockIdx.x * 128;
    int wm = wid & 3, wn = wid >> 2;

    float acc[2][8][4];
    #pragma unroll
    for (int mt = 0; mt < 2; mt++)
        #pragma unroll
        for (int nt = 0; nt < 8; nt++)
            #pragma unroll
            for (int j = 0; j < 4; j++) acc[mt][nt][j] = 0.f;

    int nch = K >> 5;

    ld_stage<CONV,DSHIFT>(Ahi, Alo, Bhi, Blo, bm, bn, K, 0, sb, tid);
    asm volatile("cp.async.commit_group;");

    // single-barrier double-buffered mainloop (R11 config)
    for (int i = 0; i < nch; i++) {
        asm volatile("cp.async.wait_group 0;");
        __syncthreads();
        if (i + 1 < nch) {
            ld_stage<CONV,DSHIFT>(Ahi, Alo, Bhi, Blo, bm, bn, K, (i + 1) << 5,
                                  sb + ((i + 1) & 1) * STAGE_B, tid);
            asm volatile("cp.async.commit_group;");
        }

        uint32_t s = sb + (i & 1) * STAGE_B;
        #pragma unroll
        for (int ks = 0; ks < 2; ks++) {
            uint32_t ah[2][4], al[2][4];
            #pragma unroll
            for (int mt = 0; mt < 2; mt++) {
                uint32_t ra = s + (uint32_t)((wm*32 + mt*16) + (lane & 15)) * (TSTR*2)
                            + ks * 32 + (lane >> 4) * 16;
                ldm4(ah[mt], ra);
                ldm4(al[mt], ra + TBYTES);
            }
            uint32_t bh[4][4], bl[4][4];
            #pragma unroll
            for (int g = 0; g < 4; g++) {
                uint32_t rb = s + 2*TBYTES + (uint32_t)((wn*64 + g*16) + (lane & 15)) * (TSTR*2)
                            + ks * 32 + (lane >> 4) * 16;
                ldm4(bh[g], rb);
                ldm4(bl[g], rb + TBYTES);
            }
            #pragma unroll
            for (int mt = 0; mt < 2; mt++)
                #pragma unroll
                for (int nt = 0; nt < 8; nt++) {
                    int g = nt >> 1, o = nt & 1;
                    mma16816(acc[mt][nt], ah[mt], bh[g][o], bh[g][o + 2]);
                    mma16816(acc[mt][nt], ah[mt], bl[g][o], bl[g][o + 2]);
                    mma16816(acc[mt][nt], al[mt], bh[g][o], bh[g][o + 2]);
                }
        }
    }

    #pragma unroll
    for (int mt = 0; mt < 2; mt++)
        #pragma unroll
        for (int nt = 0; nt < 8; nt++)
            #pragma unroll
            for (int half = 0; half < 2; half++) {
                int row = bm + wm*32 + mt*16 + (lane >> 2) + half*8;
                int col = bn + wn*64 + nt*8 + (lane & 3)*2;
                float v0 = acc[mt][nt][half*2 + 0];
                float v1 = acc[mt][nt][half*2 + 1];
                size_t o = (size_t)row * Nglob + col;
                if (EPI == 1) {
                    float2 rr = *(const float2*)(res + o);
                    *(float2*)(Cf + o) = make_float2(v0 + rr.x, v1 + rr.y);
                } else if (EPI == 2) {
                    float2 bb = *(const float2*)(bias + col);
                    v0 = fmaxf(v0 + bb.x, 0.f);
                    v1 = fmaxf(v1 + bb.y, 0.f);
                    split2(v0, v1, Chi, Clo, o);
                } else if (EPI == 5) {
                    float2 rr = *(const float2*)(res + o);
                    float2 bb = *(const float2*)(bias + col);
                    float s0 = v0 + bb.x + rr.x;
                    float s1 = v1 + bb.y + rr.y;
                    *(float2*)(Cf + o) = make_float2(s0, s1);
                    float u = uw[row];
                    float2 pv = *(const float2*)(prevp + o);
                    *(float2*)(prevp + o) = make_float2(s0 * u + pv.x * (1.f - u),
                                                        s1 * u + pv.y * (1.f - u));
                } else {  // EPI 6: fused QKV split, q-scale on first 1024 cols
                    float a = (col < 1024) ? 0.125f : 1.0f;
                    split2(v0 * a, v1 * a, Chi, Clo, o);
                }
            }
}

// ---------------- fused attention: logits + softmax -> prob hi/lo -------------
// CTA: 32 q-rows x full 512 k per (b,h). Warp w owns interleaved col groups
// g*64 + w*8 (g = 0..7), so every 128-key chunk activates all 8 warps.
#define AQ_STR 72
#define AQ_TB  (32*AQ_STR*2)    /* 4608 */
#define AK_TB  (128*AQ_STR*2)   /* 18432 */
#define ASMEM  (2*AQ_TB + 2*AK_TB)  /* 46080 */

__global__ __launch_bounds__(256, 2)
void attn_fused(const bf16* __restrict__ qkvh, const bf16* __restrict__ qkvl,
                bf16* __restrict__ wh, bf16* __restrict__ wl)
{
    extern __shared__ char smem[];
    __shared__ float sredM[8][32];
    __shared__ float sredS[8][32];
    uint32_t sb = smem_u32(smem);
    int tid = threadIdx.x, wid = tid >> 5, lane = tid & 31;
    int bz = blockIdx.y;
    int b = bz >> 4, h = bz & 15;
    int q0 = blockIdx.x * 32;
    uint32_t ksm = sb + 2*AQ_TB;

    // Q tile (32 rows x 64 d), hi+lo — loaded once
    {
        int row = tid >> 3, ch = tid & 7;
        uint32_t d = (uint32_t)(row * (AQ_STR*2) + ch * 16);
        size_t so = ((size_t)(b*512 + q0 + row)) * 3072 + h*64 + ch*8;
        cpa16(sb + d,         qkvh + so, 16);
        cpa16(sb + AQ_TB + d, qkvl + so, 16);
    }
    asm volatile("cp.async.commit_group;");

    float acc[2][8][4];
    #pragma unroll
    for (int mt = 0; mt < 2; mt++)
        #pragma unroll
        for (int g = 0; g < 8; g++)
            #pragma unroll
            for (int j = 0; j < 4; j++) acc[mt][g][j] = 0.f;

    for (int c = 0; c < 4; c++) {
        // K chunk: rows c*128..c*128+127, hi+lo
        #pragma unroll
        for (int i = 0; i < 4; i++) {
            int unit = i * 256 + tid;
            int row = unit >> 3, ch = unit & 7;
            uint32_t d = (uint32_t)(row * (AQ_STR*2) + ch * 16);
            size_t so = ((size_t)(b*512 + c*128 + row)) * 3072 + 1024 + h*64 + ch*8;
            cpa16(ksm + d,         qkvh + so, 16);
            cpa16(ksm + AK_TB + d, qkvl + so, 16);
        }
        asm volatile("cp.async.commit_group;");
        asm volatile("cp.async.wait_group 0;");
        __syncthreads();

        #pragma unroll
        for (int ks = 0; ks < 4; ks++) {
            uint32_t ah[2][4], al[2][4];
            #pragma unroll
            for (int mt = 0; mt < 2; mt++) {
                uint32_t ra = sb + (uint32_t)((mt*16 + (lane & 15)) * (AQ_STR*2))
                            + ks * 32 + (lane >> 4) * 16;
                ldm4(ah[mt], ra);
                ldm4(al[mt], ra + AQ_TB);
            }
            // B frags: tile0/2 = local rows wid*8..+7 (j=0), tile1/3 = rows 64+wid*8..+7 (j=1)
            uint32_t bh4[4], bl4[4];
            int rowb = ((lane & 8) ? 64 : 0) + wid*8 + (lane & 7);
            uint32_t rb = ksm + (uint32_t)(rowb * (AQ_STR*2)) + ks * 32 + (lane >> 4) * 16;
            ldm4(bh4, rb);
            ldm4(bl4, rb + AK_TB);
            #pragma unroll
            for (int mt = 0; mt < 2; mt++)
                #pragma unroll
                for (int j = 0; j < 2; j++) {
                    int g = 2*c + j;
                    mma16816(acc[mt][g], ah[mt], bh4[j], bh4[j + 2]);
                    mma16816(acc[mt][g], ah[mt], bl4[j], bl4[j + 2]);
                    mma16816(acc[mt][g], al[mt], bh4[j], bh4[j + 2]);
                }
        }
        __syncthreads();   // before next chunk overwrites K smem
    }

    // softmax over 512 cols: rows r = mt*16 + (lane>>2) + hf*8 (local 0..31)
    // step 1: quad-reduced max partials per warp
    #pragma unroll
    for (int mt = 0; mt < 2; mt++)
        #pragma unroll
        for (int hf = 0; hf < 2; hf++) {
            float m = -1e30f;
            #pragma unroll
            for (int g = 0; g < 8; g++) {
                m = fmaxf(m, acc[mt][g][hf*2 + 0]);
                m = fmaxf(m, acc[mt][g][hf*2 + 1]);
            }
            m = fmaxf(m, __shfl_xor_sync(0xffffffffu, m, 1));
            m = fmaxf(m, __shfl_xor_sync(0xffffffffu, m, 2));
            if ((lane & 3) == 0) sredM[wid][mt*16 + (lane >> 2) + hf*8] = m;
        }
    __syncthreads();
    // step 2: full max, exp, sum partials
    #pragma unroll
    for (int mt = 0; mt < 2; mt++)
        #pragma unroll
        for (int hf = 0; hf < 2; hf++) {
            int r = mt*16 + (lane >> 2) + hf*8;
            float m = sredM[0][r];
            #pragma unroll
            for (int w = 1; w < 8; w++) m = fmaxf(m, sredM[w][r]);
            float s = 0.f;
            #pragma unroll
            for (int g = 0; g < 8; g++) {
                float e0 = expf(acc[mt][g][hf*2 + 0] - m);
                float e1 = expf(acc[mt][g][hf*2 + 1] - m);
                acc[mt][g][hf*2 + 0] = e0;
                acc[mt][g][hf*2 + 1] = e1;
                s += e0 + e1;
            }
            s += __shfl_xor_sync(0xffffffffu, s, 1);
            s += __shfl_xor_sync(0xffffffffu, s, 2);
            if ((lane & 3) == 0) sredS[wid][r] = s;
        }
    __syncthreads();
    // step 3: normalize + split write
    #pragma unroll
    for (int mt = 0; mt < 2; mt++)
        #pragma unroll
        for (int hf = 0; hf < 2; hf++) {
            int r = mt*16 + (lane >> 2) + hf*8;
            float s = 0.f;
            #pragma unroll
            for (int w = 0; w < 8; w++) s += sredS[w][r];
            float inv = 1.f / s;
            size_t rowo = ((size_t)bz*512 + q0 + r) * 512;
            #pragma unroll
            for (int g = 0; g < 8; g++) {
                size_t o = rowo + g*64 + wid*8 + (lane & 3)*2;
                split2(acc[mt][g][hf*2 + 0] * inv, acc[mt][g][hf*2 + 1] * inv, wh, wl, o);
            }
        }
}

// ---------------- attention: ctx = w@v (per bh), tile 128x64, K=512 -----------
#define WA_B  (128*TSTR*2)   /* 10240 */
#define WB_B  (64*TSTR*2)    /* 5120 */
#define WSTAGE (2*WA_B + 2*WB_B)   /* 30720 */
#define WSMEM (2*WSTAGE)           /* 61440 */

__global__ __launch_bounds__(256, 2)
void attn_wv(const bf16* __restrict__ wh, const bf16* __restrict__ wl,
             const bf16* __restrict__ vth, const bf16* __restrict__ vtl,
             bf16* __restrict__ ctxh, bf16* __restrict__ ctxl)
{
    extern __shared__ char smem[];
    uint32_t sb = smem_u32(smem);
    int tid = threadIdx.x, wid = tid >> 5, lane = tid & 31;
    int bz = blockIdx.y;
    int b = bz >> 4, h = bz & 15;
    size_t abase = (size_t)bz*262144 + (size_t)blockIdx.x*65536;
    size_t bbase = (size_t)bz*32768;
    int wm = wid & 3, wn = wid >> 2;

    float acc[2][4][4];
    #pragma unroll
    for (int mt = 0; mt < 2; mt++)
        #pragma unroll
        for (int nt = 0; nt < 4; nt++)
            #pragma unroll
            for (int j = 0; j < 4; j++) acc[mt][nt][j] = 0.f;

    auto load_chunk = [&](int k0, uint32_t s) {
        #pragma unroll
        for (int i = 0; i < 2; i++) {
            int unit = i * 256 + tid;
            int row = unit >> 2, ch = unit & 3;
            uint32_t d = (uint32_t)(row * (TSTR*2) + ch * 16);
            size_t so = abase + (size_t)row * 512 + k0 + ch * 8;
            cpa16(s + d,        wh + so, 16);
            cpa16(s + WA_B + d, wl + so, 16);
        }
        {
            int row = tid >> 2, ch = tid & 3;
            uint32_t d = (uint32_t)(row * (TSTR*2) + ch * 16);
            size_t so = bbase + (size_t)row * 512 + k0 + ch * 8;
            cpa16(s + 2*WA_B + d,        vth + so, 16);
            cpa16(s + 2*WA_B + WB_B + d, vtl + so, 16);
        }
    };

    load_chunk(0, sb);
    asm volatile("cp.async.commit_group;");

    for (int i = 0; i < 16; i++) {
        asm volatile("cp.async.wait_group 0;");
        __syncthreads();
        if (i + 1 < 16) {
            load_chunk((i + 1) << 5, sb + ((i + 1) & 1) * WSTAGE);
            asm volatile("cp.async.commit_group;");
        }

        uint32_t s = sb + (i & 1) * WSTAGE;
        #pragma unroll
        for (int ks = 0; ks < 2; ks++) {
            uint32_t ah[2][4], al[2][4];
            #pragma unroll
            for (int mt = 0; mt < 2; mt++) {
                uint32_t ra = s + (uint32_t)((wm*32 + mt*16) + (lane & 15)) * (TSTR*2)
                            + ks * 32 + (lane >> 4) * 16;
                ldm4(ah[mt], ra);
                ldm4(al[mt], ra + WA_B);
            }
            uint32_t bh[2][4], bl[2][4];
            #pragma unroll
            for (int g = 0; g < 2; g++) {
                uint32_t rb = s + 2*WA_B + (uint32_t)((wn*32 + g*16) + (lane & 15)) * (TSTR*2)
                            + ks * 32 + (lane >> 4) * 16;
                ldm4(bh[g], rb);
                ldm4(bl[g], rb + WB_B);
            }
            #pragma unroll
            for (int mt = 0; mt < 2; mt++)
                #pragma unroll
                for (int nt = 0; nt < 4; nt++) {
                    int g = nt >> 1, o = nt & 1;
                    mma16816(acc[mt][nt], ah[mt], bh[g][o], bh[g][o + 2]);
                    mma16816(acc[mt][nt], ah[mt], bl[g][o], bl[g][o + 2]);
                    mma16816(acc[mt][nt], al[mt], bh[g][o], bh[g][o + 2]);
                }
        }
    }

    #pragma unroll
    for (int mt = 0; mt < 2; mt++)
        #pragma unroll
        for (int nt = 0; nt < 4; nt++)
            #pragma unroll
            for (int half = 0; half < 2; half++) {
                int rloc = wm*32 + mt*16 + (lane >> 2) + half*8;
                int row = b*512 + blockIdx.x*128 + rloc;
                int col = h*64 + wn*32 + nt*8 + (lane & 3)*2;
                size_t o = (size_t)row * 1024 + col;
                split2(acc[mt][nt][half*2], acc[mt][nt][half*2 + 1], ctxh, ctxl, o);
            }
}

// ---------------- fused: time/pos add + ACT halt + layernorm1 -----------------
__global__ __launch_bounds__(256) void pre_layer(
    int t, const float* __restrict__ p_w, const float* __restrict__ p_b,
    const float* __restrict__ g, const float* __restrict__ bgm)
{
    __shared__ float sh1[8], sh2[8], sh3[8];
    const float NEG_LOG_INC = -0.018024149455921103f;
    int row = blockIdx.x;
    int l   = row & 511;
    int tid = threadIdx.x;
    float* x = g_state + (size_t)row * 1024;
    float v[4];
    float sum = 0.f, dot = 0.f;
    #pragma unroll
    for (int j = 0; j < 4; j++) {
        int d = tid + 256*j;
        int i = d & 511;
        float invt = expf((float)i * NEG_LOG_INC);
        float a1 = (float)l * invt;
        float a2 = (float)t * invt;
        float sig = (d < 512) ? (sinf(a1) + sinf(a2)) : (cosf(a1) + cosf(a2));
        float val = x[d] + sig;
        x[d] = val;
        v[j] = val;
        sum += val;
        dot += val * p_w[d];
    }
    #pragma unroll
    for (int o = 16; o; o >>= 1) {
        sum += __shfl_xor_sync(0xffffffffu, sum, o);
        dot += __shfl_xor_sync(0xffffffffu, dot, o);
    }
    if ((tid & 31) == 0) { sh1[tid >> 5] = sum; sh3[tid >> 5] = dot; }
    __syncthreads();
    float tot = 0.f, dtot = 0.f;
    #pragma unroll
    for (int w = 0; w < 8; w++) { tot += sh1[w]; dtot += sh3[w]; }
    float mu = tot * (1.f / 1024.f);
    float q = 0.f;
    #pragma unroll
    for (int j = 0; j < 4; j++) { float d = v[j] - mu; q += d * d; }
    #pragma unroll
    for (int o = 16; o; o >>= 1) q += __shfl_xor_sync(0xffffffffu, q, o);
    if ((tid & 31) == 0) sh2[tid >> 5] = q;
    __syncthreads();

    if (tid == 0) {
        float p   = 1.f / (1.f + expf(-(dtot + p_b[0])));
        float hp  = g_hp[row], rem = g_rem[row], nup = g_nup[row];
        float still = (hp < 1.0f) ? 1.f : 0.f;
        float add   = hp + p * still;
        float nh    = ((add > 0.9f) ? 1.f : 0.f) * still;
        still       = ((add <= 0.9f) ? 1.f : 0.f) * still;
        hp  += p * still;
        rem += nh * (1.f - hp);
        hp  += nh * rem;
        nup += still + nh;
        g_hp[row] = hp; g_rem[row] = rem; g_nup[row] = nup;
        g_uw[row] = p * still + nh * rem;
    }

    float qt = 0.f;
    #pragma unroll
    for (int w = 0; w < 8; w++) qt += sh2[w];
    float sd  = sqrtf(qt / 1023.f);
    float inv = 1.f / (sd + 1e-6f);
    #pragma unroll
    for (int j = 0; j < 4; j++) {
        int d = tid + 256*j;
        float y = g[d] * (v[j] - mu) * inv + bgm[d];
        bf16 h = __float2bfloat16(y);
        size_t o = (size_t)row * 1024 + d;
        g_xnh[o] = h;
        g_xnl[o] = __float2bfloat16(y - __bfloat162float(h));
    }
}

// ---------------- misc elementwise --------------------------------------------
__global__ void embed_init(const int* __restrict__ X, const float* __restrict__ emb) {
    int idx = blockIdx.x * 256 + threadIdx.x;
    int row = idx >> 10;
    int d   = idx & 1023;
    g_state[idx] = emb[(size_t)X[row] * 1024 + d];
    g_prev[idx]  = 0.f;
}

__global__ void zero_act() {
    int i = blockIdx.x * 256 + threadIdx.x;
    if (i < ROWS_) { g_hp[i] = 0.f; g_rem[i] = 0.f; g_nup[i] = 0.f; }
}

// layernorm (fp32 in) -> bf16 hi/lo split outputs  (ln2)
__global__ __launch_bounds__(256) void layernorm_k(
    const float* __restrict__ in, bf16* __restrict__ ohi, bf16* __restrict__ olo,
    const float* __restrict__ g, const float* __restrict__ b)
{
    __shared__ float sh1[8], sh2[8];
    int row = blockIdx.x;
    int tid = threadIdx.x;
    const float* x = in + (size_t)row * 1024;
    float v[4];
    #pragma unroll
    for (int j = 0; j < 4; j++) v[j] = x[tid + 256*j];
    float s = v[0] + v[1] + v[2] + v[3];
    #pragma unroll
    for (int o = 16; o; o >>= 1) s += __shfl_xor_sync(0xffffffffu, s, o);
    if ((tid & 31) == 0) sh1[tid >> 5] = s;
    __syncthreads();
    float tot = 0.f;
    #pragma unroll
    for (int w = 0; w < 8; w++) tot += sh1[w];
    float mu = tot * (1.f / 1024.f);
    float q = 0.f;
    #pragma unroll
    for (int j = 0; j < 4; j++) { float d = v[j] - mu; q += d * d; }
    #pragma unroll
    for (int o = 16; o; o >>= 1) q += __shfl_xor_sync(0xffffffffu, q, o);
    if ((tid & 31) == 0) sh2[tid >> 5] = q;
    __syncthreads();
    float qt = 0.f;
    #pragma unroll
    for (int w = 0; w < 8; w++) qt += sh2[w];
    float sd  = sqrtf(qt / 1023.f);
    float inv = 1.f / (sd + 1e-6f);
    #pragma unroll
    for (int j = 0; j < 4; j++) {
        int d = tid + 256*j;
        float y = g[d] * (v[j] - mu) * inv + b[d];
        bf16 h = __float2bfloat16(y);
        size_t o = (size_t)row * 1024 + d;
        ohi[o] = h;
        olo[o] = __float2bfloat16(y - __bfloat162float(h));
    }
}

// ---------------- head --------------------------------------------------------
__global__ __launch_bounds__(256) void head_out(
    const float* __restrict__ W_out, const float* __restrict__ b_out, float* __restrict__ out)
{
    __shared__ float sh[4][256];
    int b = blockIdx.x;
    int tid = threadIdx.x;
    float sum[4] = {0.f, 0.f, 0.f, 0.f};
    for (int l = 0; l < 512; l++) {
        const float* p = g_prev + ((size_t)(b*512 + l)) * 1024;
        #pragma unroll
        for (int j = 0; j < 4; j++) sum[j] += p[tid + 256*j];
    }
    float part[4] = {0.f, 0.f, 0.f, 0.f};
    #pragma unroll
    for (int j = 0; j < 4; j++) {
        int d = tid + 256*j;
        float m = sum[j] * (1.f / 512.f);
        #pragma unroll
        for (int o = 0; o < 4; o++) part[o] += m * W_out[d*4 + o];
    }
    #pragma unroll
    for (int o = 0; o < 4; o++) sh[o][tid] = part[o];
    __syncthreads();
    for (int s = 128; s > 0; s >>= 1) {
        if (tid < s)
            #pragma unroll
            for (int o = 0; o < 4; o++) sh[o][tid] += sh[o][tid + s];
        __syncthreads();
    }
    if (tid == 0) {
        float a[4];
        #pragma unroll
        for (int o = 0; o < 4; o++) { a[o] = sh[o][0] + b_out[o]; out[b*4 + o] = a[o]; }
        float mx = fmaxf(fmaxf(a[0], a[1]), fmaxf(a[2], a[3]));
        float e[4], s = 0.f;
        #pragma unroll
        for (int o = 0; o < 4; o++) { e[o] = expf(a[o] - mx); s += e[o]; }
        #pragma unroll
        for (int o = 0; o < 4; o++) out[32 + b*4 + o] = e[o] / s;
    }
}

__global__ void tail_out(float* __restrict__ out) {
    int i = blockIdx.x * 256 + threadIdx.x;
    out[64 + i]        = g_rem[i];
    out[64 + 4096 + i] = g_nup[i];
}

// ---------------- launcher ----------------------------------------------------
extern "C" void kernel_launch(void* const* d_in, const int* in_sizes, int n_in,
                              void* d_out, int out_size) {
    const int*   X     = (const int*)  d_in[0];
    const float* emb   = (const float*)d_in[1];
    const float* p_w   = (const float*)d_in[2];
    const float* p_b   = (const float*)d_in[3];
    const float* Wq    = (const float*)d_in[4];
    const float* Wk    = (const float*)d_in[5];
    const float* Wv    = (const float*)d_in[6];
    const float* Wo    = (const float*)d_in[7];
    const float* ln1_g = (const float*)d_in[8];
    const float* ln1_b = (const float*)d_in[9];
    const float* ln2_g = (const float*)d_in[10];
    const float* ln2_b = (const float*)d_in[11];
    const float* K1    = (const float*)d_in[12];
    const float* c1_b  = (const float*)d_in[13];
    const float* K2    = (const float*)d_in[14];
    const float* c2_b  = (const float*)d_in[15];
    const float* W_out = (const float*)d_in[16];
    const float* b_out = (const float*)d_in[17];
    float* out = (float*)d_out;

    float *state, *prevp, *uw;
    bf16 *xnh, *xnl, *qkvh, *qkvl, *vth, *vtl, *ctxh, *ctxl, *wh, *wl, *hh, *hl;
    bf16 *Wqkvh, *Wqkvl, *Woh, *Wol, *K1h, *K1l, *K2h, *K2l;
    cudaGetSymbolAddress((void**)&state, g_state);
    cudaGetSymbolAddress((void**)&prevp, g_prev);
    cudaGetSymbolAddress((void**)&uw,    g_uw);
    cudaGetSymbolAddress((void**)&xnh,   g_xnh);   cudaGetSymbolAddress((void**)&xnl,  g_xnl);
    cudaGetSymbolAddress((void**)&qkvh,  g_qkvh);  cudaGetSymbolAddress((void**)&qkvl, g_qkvl);
    cudaGetSymbolAddress((void**)&vth,   g_vth);   cudaGetSymbolAddress((void**)&vtl,  g_vtl);
    cudaGetSymbolAddress((void**)&ctxh,  g_ctxh);  cudaGetSymbolAddress((void**)&ctxl, g_ctxl);
    cudaGetSymbolAddress((void**)&wh,    g_wh);    cudaGetSymbolAddress((void**)&wl,   g_wl);
    cudaGetSymbolAddress((void**)&hh,    g_hh);    cudaGetSymbolAddress((void**)&hl,   g_hl);
    cudaGetSymbolAddress((void**)&Wqkvh, g_Wqkvh); cudaGetSymbolAddress((void**)&Wqkvl,g_Wqkvl);
    cudaGetSymbolAddress((void**)&Woh,   g_Woh);   cudaGetSymbolAddress((void**)&Wol,  g_Wol);
    cudaGetSymbolAddress((void**)&K1h,   g_K1h);   cudaGetSymbolAddress((void**)&K1l,  g_K1l);
    cudaGetSymbolAddress((void**)&K2h,   g_K2h);   cudaGetSymbolAddress((void**)&K2l,  g_K2l);

    cudaFuncSetAttribute(mm_gemm<0,0,1>,  cudaFuncAttributeMaxDynamicSharedMemorySize, SMEM_SZ);
    cudaFuncSetAttribute(mm_gemm<0,0,6>,  cudaFuncAttributeMaxDynamicSharedMemorySize, SMEM_SZ);
    cudaFuncSetAttribute(mm_gemm<1,10,2>, cudaFuncAttributeMaxDynamicSharedMemorySize, SMEM_SZ);
    cudaFuncSetAttribute(mm_gemm<1,12,5>, cudaFuncAttributeMaxDynamicSharedMemorySize, SMEM_SZ);
    cudaFuncSetAttribute(attn_fused, cudaFuncAttributeMaxDynamicSharedMemorySize, ASMEM);
    cudaFuncSetAttribute(attn_wv,    cudaFuncAttributeMaxDynamicSharedMemorySize, WSMEM);

    dim3 tb(32, 8);
    prep_square<<<dim3(32, 32, 4), tb>>>(Wq, Wk, Wv, Wo, Wqkvh, Wqkvl, Woh, Wol);
    prep_conv<<<24576, tb>>>(K1, K2, K1h, K1l, K2h, K2l);
    embed_init<<<NST_/256, 256>>>(X, emb);
    zero_act<<<16, 256>>>();

    for (int t = 0; t < NL_; t++) {
        pre_layer<<<ROWS_, 256>>>(t, p_w, p_b, ln1_g, ln1_b);

        // fused QKV: N=3072
        mm_gemm<0,0,6><<<dim3(24, 32), 256, SMEM_SZ>>>(xnh, xnl, Wqkvh, Wqkvl,
            nullptr, qkvh, qkvl, nullptr, nullptr, nullptr, nullptr, 3*D_, D_);

        transpose_v<<<dim3(32, 16, 16), tb>>>(qkvh, qkvl, vth, vtl);

        attn_fused<<<dim3(16, 128), 256, ASMEM>>>(qkvh, qkvl, wh, wl);
        attn_wv<<<dim3(4, B_*H_), 256, WSMEM>>>(wh, wl, vth, vtl, ctxh, ctxl);

        dim3 gp(D_/128, ROWS_/128);
        mm_gemm<0,0,1><<<gp, 256, SMEM_SZ>>>(ctxh, ctxl, Woh, Wol,
            state, nullptr, nullptr, state, nullptr, nullptr, nullptr, D_, D_);
        layernorm_k<<<ROWS_, 256>>>(state, xnh, xnl, ln2_g, ln2_b);

        mm_gemm<1,10,2><<<dim3(F_/128, ROWS_/128), 256, SMEM_SZ>>>(xnh, xnl, K1h, K1l,
            nullptr, hh, hl, nullptr, c1_b, nullptr, nullptr, F_, 3*D_);
        // conv2 + fused prev_update
        mm_gemm<1,12,5><<<gp, 256, SMEM_SZ>>>(hh, hl, K2h, K2l,
            state, nullptr, nullptr, state, c2_b, uw, prevp, D_, 3*F_);
    }

    head_out<<<B_, 256>>>(W_out, b_out, out);
    tail_out<<<ROWS_/256, 256>>>(out);
}

// round 16
// speedup vs baseline: 1.1097x; 1.0064x over previous
#include <cuda_runtime.h>
#include <cuda_bf16.h>
#include <cstdint>
#include <math.h>

#define B_    8
#define L_    512
#define D_    1024
#define H_    16
#define F_    4096
#define NL_   6
#define ROWS_ (B_*L_)          /* 4096 */
#define NST_  (ROWS_*D_)       /* 4194304 */

typedef __nv_bfloat16 bf16;

// ---------------- scratch (device globals; no allocation allowed) ------------
__device__ float g_state[NST_];
__device__ float g_prev [NST_];

__device__ bf16 g_xnh[NST_],  g_xnl[NST_];
__device__ bf16 g_qkvh[(size_t)ROWS_*3*D_], g_qkvl[(size_t)ROWS_*3*D_];
__device__ bf16 g_vth[NST_],  g_vtl[NST_];
__device__ bf16 g_ctxh[NST_], g_ctxl[NST_];
__device__ bf16 g_wh[(size_t)B_*H_*L_*L_], g_wl[(size_t)B_*H_*L_*L_];
__device__ bf16 g_hh[(size_t)ROWS_*F_], g_hl[(size_t)ROWS_*F_];

// transposed+split weights [N][K]
__device__ bf16 g_Wqkvh[3*D_*D_], g_Wqkvl[3*D_*D_];
__device__ bf16 g_Woh[D_*D_], g_Wol[D_*D_];
__device__ bf16 g_K1h[(size_t)F_*3*D_], g_K1l[(size_t)F_*3*D_];
__device__ bf16 g_K2h[(size_t)D_*3*F_], g_K2l[(size_t)D_*3*F_];

__device__ float g_hp [ROWS_];
__device__ float g_rem[ROWS_];
__device__ float g_nup[ROWS_];
__device__ float g_uw [ROWS_];

// precomputed timing/positional signals + head partials
__device__ float g_tsig[512*1024];
__device__ float g_psig[NL_*1024];
__device__ float g_hpart[64*1024];

// ---------------- PTX helpers -------------------------------------------------
__device__ __forceinline__ uint32_t smem_u32(const void* p) {
    uint32_t a;
    asm("{ .reg .u64 t; cvta.to.shared.u64 t, %1; cvt.u32.u64 %0, t; }" : "=r"(a) : "l"(p));
    return a;
}
__device__ __forceinline__ void cpa16(uint32_t dst, const void* src, int sz) {
    asm volatile("cp.async.cg.shared.global [%0], [%1], 16, %2;" :: "r"(dst), "l"(src), "r"(sz));
}
__device__ __forceinline__ void ldm4(uint32_t* r, uint32_t addr) {
    asm volatile("ldmatrix.sync.aligned.m8n8.x4.shared.b16 {%0,%1,%2,%3}, [%4];"
        : "=r"(r[0]), "=r"(r[1]), "=r"(r[2]), "=r"(r[3]) : "r"(addr));
}
__device__ __forceinline__ void mma16816(float* c, const uint32_t* a, uint32_t b0, uint32_t b1) {
    asm volatile("mma.sync.aligned.m16n8k16.row.col.f32.bf16.bf16.f32 "
        "{%0,%1,%2,%3}, {%4,%5,%6,%7}, {%8,%9}, {%0,%1,%2,%3};"
        : "+f"(c[0]), "+f"(c[1]), "+f"(c[2]), "+f"(c[3])
        : "r"(a[0]), "r"(a[1]), "r"(a[2]), "r"(a[3]), "r"(b0), "r"(b1));
}
__device__ __forceinline__ void split2(float v0, float v1, bf16* hi, bf16* lo, size_t o) {
    bf16 h0 = __float2bfloat16(v0), h1 = __float2bfloat16(v1);
    __nv_bfloat162 hh2; hh2.x = h0; hh2.y = h1;
    *(__nv_bfloat162*)(hi + o) = hh2;
    __nv_bfloat162 ll2;
    ll2.x = __float2bfloat16(v0 - __bfloat162float(h0));
    ll2.y = __float2bfloat16(v1 - __bfloat162float(h1));
    *(__nv_bfloat162*)(lo + o) = ll2;
}

// ---------------- weight transpose + bf16 split ------------------------------
__device__ __forceinline__ void tsplit_body(const float* __restrict__ in, int inRowLen,
                                            bf16* __restrict__ ohi, bf16* __restrict__ olo,
                                            int outStride, int n0, int k0)
{
    __shared__ float t[32][33];
    int tx = threadIdx.x, ty = threadIdx.y;
    #pragma unroll
    for (int i = 0; i < 32; i += 8)
        t[ty + i][tx] = in[(size_t)(k0 + ty + i) * inRowLen + n0 + tx];
    __syncthreads();
    #pragma unroll
    for (int i = 0; i < 32; i += 8) {
        float v = t[tx][ty + i];
        bf16 h = __float2bfloat16(v);
        size_t o = (size_t)(n0 + ty + i) * outStride + k0 + tx;
        ohi[o] = h;
        olo[o] = __float2bfloat16(v - __bfloat162float(h));
    }
}

__global__ void prep_square(const float* __restrict__ Wq, const float* __restrict__ Wk,
                            const float* __restrict__ Wv, const float* __restrict__ Wo,
                            bf16* __restrict__ Wqkvh, bf16* __restrict__ Wqkvl,
                            bf16* __restrict__ Woh, bf16* __restrict__ Wol)
{
    int z = blockIdx.z;
    const float* in = (z == 0) ? Wq : (z == 1) ? Wk : (z == 2) ? Wv : Wo;
    bf16* oh = (z == 3) ? Woh : (Wqkvh + (size_t)z * 1024 * 1024);
    bf16* ol = (z == 3) ? Wol : (Wqkvl + (size_t)z * 1024 * 1024);
    tsplit_body(in, 1024, oh, ol, 1024, blockIdx.x * 32, blockIdx.y * 32);
}

__global__ void prep_conv(const float* __restrict__ K1, const float* __restrict__ K2,
                          bf16* __restrict__ K1h, bf16* __restrict__ K1l,
                          bf16* __restrict__ K2h, bf16* __restrict__ K2l)
{
    int id = blockIdx.x;
    if (id < 12288) {
        int w = id / 4096, r = id % 4096;
        int n0 = (r % 128) * 32, k0 = (r / 128) * 32;
        tsplit_body(K1 + (size_t)w * 1024 * 4096, 4096,
                    K1h + (size_t)w * 1024, K1l + (size_t)w * 1024, 3072, n0, k0);
    } else {
        id -= 12288;
        int w = id / 4096, r = id % 4096;
        int n0 = (r % 32) * 32, k0 = (r / 32) * 32;
        tsplit_body(K2 + (size_t)w * 4096 * 1024, 1024,
                    K2h + (size_t)w * 4096, K2l + (size_t)w * 4096, 12288, n0, k0);
    }
}

// precompute time/pos signals: blocks 0..511 -> tsig rows, 512..517 -> psig rows
__global__ void init_sig() {
    const float NEG_LOG_INC = -0.018024149455921103f;  // -ln(10000)/511
    int r = blockIdx.x;
    int tid = threadIdx.x;
    #pragma unroll
    for (int j = 0; j < 4; j++) {
        int d = tid + 256*j;
        int i = d & 511;
        float invt = expf((float)i * NEG_LOG_INC);
        if (r < 512) {
            float a = (float)r * invt;
            g_tsig[r*1024 + d] = (d < 512) ? sinf(a) : cosf(a);
        } else {
            int t = r - 512;
            float a = (float)t * invt;
            g_psig[t*1024 + d] = (d < 512) ? sinf(a) : cosf(a);
        }
    }
}

// per-batch bf16 transpose of the V part of packed qkv
__global__ void transpose_v(const bf16* __restrict__ inh, const bf16* __restrict__ inl,
                            bf16* __restrict__ outh, bf16* __restrict__ outl)
{
    __shared__ bf16 t[32][33];
    int b = blockIdx.z >> 1, sel = blockIdx.z & 1;
    const bf16* in = sel ? inl : inh;
    bf16* out = sel ? outl : outh;
    int c0 = blockIdx.x * 32, l0 = blockIdx.y * 32;
    int tx = threadIdx.x, ty = threadIdx.y;
    #pragma unroll
    for (int i = 0; i < 32; i += 8)
        t[ty + i][tx] = in[((size_t)(b * 512 + l0 + ty + i)) * 3072 + 2048 + c0 + tx];
    __syncthreads();
    #pragma unroll
    for (int i = 0; i < 32; i += 8)
        out[((size_t)(b * 1024 + c0 + ty + i)) * 512 + l0 + tx] = t[tx][ty + i];
}

// ---------------- mma.sync GEMM (128x128 tile, 2-stage, occ 2 — R11 config) ---
#define TSTR    40
#define TBYTES  (128*TSTR*2)       /* 10240 */
#define STAGE_B (4*TBYTES)         /* 40960 */
#define SMEM_SZ (2*STAGE_B)        /* 81920 */

__device__ __forceinline__ void ld_plain(const bf16* __restrict__ src, int row0, int K,
                                         int k0, uint32_t sbase, int tid)
{
    #pragma unroll
    for (int i = 0; i < 2; i++) {
        int unit = i * 256 + tid;
        int row = unit >> 2, ch = unit & 3;
        cpa16(sbase + row * (TSTR*2) + ch * 16,
              src + (size_t)(row0 + row) * K + k0 + ch * 8, 16);
    }
}

template<int DSHIFT>
__device__ __forceinline__ void ld_conv(const bf16* __restrict__ src, int bm,
                                        int k0, uint32_t sbase, int tid)
{
    int w  = k0 >> DSHIFT;
    int cb = k0 & ((1 << DSHIFT) - 1);
    #pragma unroll
    for (int i = 0; i < 2; i++) {
        int unit = i * 256 + tid;
        int row = unit >> 2, ch = unit & 3;
        int r = bm + row;
        int b = r >> 9;
        int l = (r & 511) + w - 1;
        int ok = ((unsigned)l < 512u);
        int lc = ok ? l : 0;
        cpa16(sbase + row * (TSTR*2) + ch * 16,
              src + (((size_t)(b * 512 + lc)) << DSHIFT) + cb + ch * 8, ok ? 16 : 0);
    }
}

template<int CONV, int DSHIFT>
__device__ __forceinline__ void ld_stage(const bf16* __restrict__ Ahi, const bf16* __restrict__ Alo,
                                         const bf16* __restrict__ Bhi, const bf16* __restrict__ Blo,
                                         int bm, int bn, int K, int k0, uint32_t s, int tid)
{
    if (CONV) { ld_conv<DSHIFT>(Ahi, bm, k0, s, tid); ld_conv<DSHIFT>(Alo, bm, k0, s + TBYTES, tid); }
    else      { ld_plain(Ahi, bm, K, k0, s, tid);      ld_plain(Alo, bm, K, k0, s + TBYTES, tid); }
    ld_plain(Bhi, bn, K, k0, s + 2*TBYTES, tid);
    ld_plain(Blo, bn, K, k0, s + 3*TBYTES, tid);
}

template<int CONV, int DSHIFT, int EPI>
__global__ __launch_bounds__(256, 2)
void mm_gemm(const bf16* __restrict__ Ahi, const bf16* __restrict__ Alo,
             const bf16* __restrict__ Bhi, const bf16* __restrict__ Blo,
             float* __restrict__ Cf, bf16* __restrict__ Chi, bf16* __restrict__ Clo,
             const float* __restrict__ res, const float* __restrict__ bias,
             const float* __restrict__ uw, float* __restrict__ prevp,
             int Nglob, int K)
{
    extern __shared__ char smem[];
    uint32_t sb = smem_u32(smem);
    int tid = threadIdx.x, wid = tid >> 5, lane = tid & 31;
    int bm = blockIdx.y * 128, bn = blockIdx.x * 128;
    int wm = wid & 3, wn = wid >> 2;

    float acc[2][8][4];
    #pragma unroll
    for (int mt = 0; mt < 2; mt++)
        #pragma unroll
        for (int nt = 0; nt < 8; nt++)
            #pragma unroll
            for (int j = 0; j < 4; j++) acc[mt][nt][j] = 0.f;

    int nch = K >> 5;

    ld_stage<CONV,DSHIFT>(Ahi, Alo, Bhi, Blo, bm, bn, K, 0, sb, tid);
    asm volatile("cp.async.commit_group;");

    for (int i = 0; i < nch; i++) {
        asm volatile("cp.async.wait_group 0;");
        __syncthreads();
        if (i + 1 < nch) {
            ld_stage<CONV,DSHIFT>(Ahi, Alo, Bhi, Blo, bm, bn, K, (i + 1) << 5,
                                  sb + ((i + 1) & 1) * STAGE_B, tid);
            asm volatile("cp.async.commit_group;");
        }

        uint32_t s = sb + (i & 1) * STAGE_B;
        #pragma unroll
        for (int ks = 0; ks < 2; ks++) {
            uint32_t ah[2][4], al[2][4];
            #pragma unroll
            for (int mt = 0; mt < 2; mt++) {
                uint32_t ra = s + (uint32_t)((wm*32 + mt*16) + (lane & 15)) * (TSTR*2)
                            + ks * 32 + (lane >> 4) * 16;
                ldm4(ah[mt], ra);
                ldm4(al[mt], ra + TBYTES);
            }
            uint32_t bh[4][4], bl[4][4];
            #pragma unroll
            for (int g = 0; g < 4; g++) {
                uint32_t rb = s + 2*TBYTES + (uint32_t)((wn*64 + g*16) + (lane & 15)) * (TSTR*2)
                            + ks * 32 + (lane >> 4) * 16;
                ldm4(bh[g], rb);
                ldm4(bl[g], rb + TBYTES);
            }
            #pragma unroll
            for (int mt = 0; mt < 2; mt++)
                #pragma unroll
                for (int nt = 0; nt < 8; nt++) {
                    int g = nt >> 1, o = nt & 1;
                    mma16816(acc[mt][nt], ah[mt], bh[g][o], bh[g][o + 2]);
                    mma16816(acc[mt][nt], ah[mt], bl[g][o], bl[g][o + 2]);
                    mma16816(acc[mt][nt], al[mt], bh[g][o], bh[g][o + 2]);
                }
        }
    }

    #pragma unroll
    for (int mt = 0; mt < 2; mt++)
        #pragma unroll
        for (int nt = 0; nt < 8; nt++)
            #pragma unroll
            for (int half = 0; half < 2; half++) {
                int row = bm + wm*32 + mt*16 + (lane >> 2) + half*8;
                int col = bn + wn*64 + nt*8 + (lane & 3)*2;
                float v0 = acc[mt][nt][half*2 + 0];
                float v1 = acc[mt][nt][half*2 + 1];
                size_t o = (size_t)row * Nglob + col;
                if (EPI == 1) {
                    float2 rr = *(const float2*)(res + o);
                    *(float2*)(Cf + o) = make_float2(v0 + rr.x, v1 + rr.y);
                } else if (EPI == 2) {
                    float2 bb = *(const float2*)(bias + col);
                    v0 = fmaxf(v0 + bb.x, 0.f);
                    v1 = fmaxf(v1 + bb.y, 0.f);
                    split2(v0, v1, Chi, Clo, o);
                } else if (EPI == 5) {
                    float2 rr = *(const float2*)(res + o);
                    float2 bb = *(const float2*)(bias + col);
                    float s0 = v0 + bb.x + rr.x;
                    float s1 = v1 + bb.y + rr.y;
                    *(float2*)(Cf + o) = make_float2(s0, s1);
                    float u = uw[row];
                    float2 pv = *(const float2*)(prevp + o);
                    *(float2*)(prevp + o) = make_float2(s0 * u + pv.x * (1.f - u),
                                                        s1 * u + pv.y * (1.f - u));
                } else {
                    float a = (col < 1024) ? 0.125f : 1.0f;
                    split2(v0 * a, v1 * a, Chi, Clo, o);
                }
            }
}

// ---------------- fused attention: logits + softmax -> prob hi/lo -------------
#define AQ_STR 72
#define AQ_TB  (32*AQ_STR*2)    /* 4608 */
#define AK_TB  (128*AQ_STR*2)   /* 18432 */
#define ASMEM  (2*AQ_TB + 2*AK_TB)  /* 46080 */

__global__ __launch_bounds__(256, 2)
void attn_fused(const bf16* __restrict__ qkvh, const bf16* __restrict__ qkvl,
                bf16* __restrict__ wh, bf16* __restrict__ wl)
{
    extern __shared__ char smem[];
    __shared__ float sredM[8][32];
    __shared__ float sredS[8][32];
    uint32_t sb = smem_u32(smem);
    int tid = threadIdx.x, wid = tid >> 5, lane = tid & 31;
    int bz = blockIdx.y;
    int b = bz >> 4, h = bz & 15;
    int q0 = blockIdx.x * 32;
    uint32_t ksm = sb + 2*AQ_TB;

    {
        int row = tid >> 3, ch = tid & 7;
        uint32_t d = (uint32_t)(row * (AQ_STR*2) + ch * 16);
        size_t so = ((size_t)(b*512 + q0 + row)) * 3072 + h*64 + ch*8;
        cpa16(sb + d,         qkvh + so, 16);
        cpa16(sb + AQ_TB + d, qkvl + so, 16);
    }
    asm volatile("cp.async.commit_group;");

    float acc[2][8][4];
    #pragma unroll
    for (int mt = 0; mt < 2; mt++)
        #pragma unroll
        for (int g = 0; g < 8; g++)
            #pragma unroll
            for (int j = 0; j < 4; j++) acc[mt][g][j] = 0.f;

    for (int c = 0; c < 4; c++) {
        #pragma unroll
        for (int i = 0; i < 4; i++) {
            int unit = i * 256 + tid;
            int row = unit >> 3, ch = unit & 7;
            uint32_t d = (uint32_t)(row * (AQ_STR*2) + ch * 16);
            size_t so = ((size_t)(b*512 + c*128 + row)) * 3072 + 1024 + h*64 + ch*8;
            cpa16(ksm + d,         qkvh + so, 16);
            cpa16(ksm + AK_TB + d, qkvl + so, 16);
        }
        asm volatile("cp.async.commit_group;");
        asm volatile("cp.async.wait_group 0;");
        __syncthreads();

        #pragma unroll
        for (int ks = 0; ks < 4; ks++) {
            uint32_t ah[2][4], al[2][4];
            #pragma unroll
            for (int mt = 0; mt < 2; mt++) {
                uint32_t ra = sb + (uint32_t)((mt*16 + (lane & 15)) * (AQ_STR*2))
                            + ks * 32 + (lane >> 4) * 16;
                ldm4(ah[mt], ra);
                ldm4(al[mt], ra + AQ_TB);
            }
            uint32_t bh4[4], bl4[4];
            int rowb = ((lane & 8) ? 64 : 0) + wid*8 + (lane & 7);
            uint32_t rb = ksm + (uint32_t)(rowb * (AQ_STR*2)) + ks * 32 + (lane >> 4) * 16;
            ldm4(bh4, rb);
            ldm4(bl4, rb + AK_TB);
            #pragma unroll
            for (int mt = 0; mt < 2; mt++)
                #pragma unroll
                for (int j = 0; j < 2; j++) {
                    int g = 2*c + j;
                    mma16816(acc[mt][g], ah[mt], bh4[j], bh4[j + 2]);
                    mma16816(acc[mt][g], ah[mt], bl4[j], bl4[j + 2]);
                    mma16816(acc[mt][g], al[mt], bh4[j], bh4[j + 2]);
                }
        }
        __syncthreads();
    }

    #pragma unroll
    for (int mt = 0; mt < 2; mt++)
        #pragma unroll
        for (int hf = 0; hf < 2; hf++) {
            float m = -1e30f;
            #pragma unroll
            for (int g = 0; g < 8; g++) {
                m = fmaxf(m, acc[mt][g][hf*2 + 0]);
                m = fmaxf(m, acc[mt][g][hf*2 + 1]);
            }
            m = fmaxf(m, __shfl_xor_sync(0xffffffffu, m, 1));
            m = fmaxf(m, __shfl_xor_sync(0xffffffffu, m, 2));
            if ((lane & 3) == 0) sredM[wid][mt*16 + (lane >> 2) + hf*8] = m;
        }
    __syncthreads();
    #pragma unroll
    for (int mt = 0; mt < 2; mt++)
        #pragma unroll
        for (int hf = 0; hf < 2; hf++) {
            int r = mt*16 + (lane >> 2) + hf*8;
            float m = sredM[0][r];
            #pragma unroll
            for (int w = 1; w < 8; w++) m = fmaxf(m, sredM[w][r]);
            float s = 0.f;
            #pragma unroll
            for (int g = 0; g < 8; g++) {
                float e0 = expf(acc[mt][g][hf*2 + 0] - m);
                float e1 = expf(acc[mt][g][hf*2 + 1] - m);
                acc[mt][g][hf*2 + 0] = e0;
                acc[mt][g][hf*2 + 1] = e1;
                s += e0 + e1;
            }
            s += __shfl_xor_sync(0xffffffffu, s, 1);
            s += __shfl_xor_sync(0xffffffffu, s, 2);
            if ((lane & 3) == 0) sredS[wid][r] = s;
        }
    __syncthreads();
    #pragma unroll
    for (int mt = 0; mt < 2; mt++)
        #pragma unroll
        for (int hf = 0; hf < 2; hf++) {
            int r = mt*16 + (lane >> 2) + hf*8;
            float s = 0.f;
            #pragma unroll
            for (int w = 0; w < 8; w++) s += sredS[w][r];
            float inv = 1.f / s;
            size_t rowo = ((size_t)bz*512 + q0 + r) * 512;
            #pragma unroll
            for (int g = 0; g < 8; g++) {
                size_t o = rowo + g*64 + wid*8 + (lane & 3)*2;
                split2(acc[mt][g][hf*2 + 0] * inv, acc[mt][g][hf*2 + 1] * inv, wh, wl, o);
            }
        }
}

// ---------------- attention: ctx = w@v (per bh), tile 128x64, K=512 -----------
#define WA_B  (128*TSTR*2)   /* 10240 */
#define WB_B  (64*TSTR*2)    /* 5120 */
#define WSTAGE (2*WA_B + 2*WB_B)   /* 30720 */
#define WSMEM (2*WSTAGE)           /* 61440 */

__global__ __launch_bounds__(256, 2)
void attn_wv(const bf16* __restrict__ wh, const bf16* __restrict__ wl,
             const bf16* __restrict__ vth, const bf16* __restrict__ vtl,
             bf16* __restrict__ ctxh, bf16* __restrict__ ctxl)
{
    extern __shared__ char smem[];
    uint32_t sb = smem_u32(smem);
    int tid = threadIdx.x, wid = tid >> 5, lane = tid & 31;
    int bz = blockIdx.y;
    int b = bz >> 4, h = bz & 15;
    size_t abase = (size_t)bz*262144 + (size_t)blockIdx.x*65536;
    size_t bbase = (size_t)bz*32768;
    int wm = wid & 3, wn = wid >> 2;

    float acc[2][4][4];
    #pragma unroll
    for (int mt = 0; mt < 2; mt++)
        #pragma unroll
        for (int nt = 0; nt < 4; nt++)
            #pragma unroll
            for (int j = 0; j < 4; j++) acc[mt][nt][j] = 0.f;

    auto load_chunk = [&](int k0, uint32_t s) {
        #pragma unroll
        for (int i = 0; i < 2; i++) {
            int unit = i * 256 + tid;
            int row = unit >> 2, ch = unit & 3;
            uint32_t d = (uint32_t)(row * (TSTR*2) + ch * 16);
            size_t so = abase + (size_t)row * 512 + k0 + ch * 8;
            cpa16(s + d,        wh + so, 16);
            cpa16(s + WA_B + d, wl + so, 16);
        }
        {
            int row = tid >> 2, ch = tid & 3;
            uint32_t d = (uint32_t)(row * (TSTR*2) + ch * 16);
            size_t so = bbase + (size_t)row * 512 + k0 + ch * 8;
            cpa16(s + 2*WA_B + d,        vth + so, 16);
            cpa16(s + 2*WA_B + WB_B + d, vtl + so, 16);
        }
    };

    load_chunk(0, sb);
    asm volatile("cp.async.commit_group;");

    for (int i = 0; i < 16; i++) {
        asm volatile("cp.async.wait_group 0;");
        __syncthreads();
        if (i + 1 < 16) {
            load_chunk((i + 1) << 5, sb + ((i + 1) & 1) * WSTAGE);
            asm volatile("cp.async.commit_group;");
        }

        uint32_t s = sb + (i & 1) * WSTAGE;
        #pragma unroll
        for (int ks = 0; ks < 2; ks++) {
            uint32_t ah[2][4], al[2][4];
            #pragma unroll
            for (int mt = 0; mt < 2; mt++) {
                uint32_t ra = s + (uint32_t)((wm*32 + mt*16) + (lane & 15)) * (TSTR*2)
                            + ks * 32 + (lane >> 4) * 16;
                ldm4(ah[mt], ra);
                ldm4(al[mt], ra + WA_B);
            }
            uint32_t bh[2][4], bl[2][4];
            #pragma unroll
            for (int g = 0; g < 2; g++) {
                uint32_t rb = s + 2*WA_B + (uint32_t)((wn*32 + g*16) + (lane & 15)) * (TSTR*2)
                            + ks * 32 + (lane >> 4) * 16;
                ldm4(bh[g], rb);
                ldm4(bl[g], rb + WB_B);
            }
            #pragma unroll
            for (int mt = 0; mt < 2; mt++)
                #pragma unroll
                for (int nt = 0; nt < 4; nt++) {
                    int g = nt >> 1, o = nt & 1;
                    mma16816(acc[mt][nt], ah[mt], bh[g][o], bh[g][o + 2]);
                    mma16816(acc[mt][nt], ah[mt], bl[g][o], bl[g][o + 2]);
                    mma16816(acc[mt][nt], al[mt], bh[g][o], bh[g][o + 2]);
                }
        }
    }

    #pragma unroll
    for (int mt = 0; mt < 2; mt++)
        #pragma unroll
        for (int nt = 0; nt < 4; nt++)
            #pragma unroll
            for (int half = 0; half < 2; half++) {
                int rloc = wm*32 + mt*16 + (lane >> 2) + half*8;
                int row = b*512 + blockIdx.x*128 + rloc;
                int col = h*64 + wn*32 + nt*8 + (lane & 3)*2;
                size_t o = (size_t)row * 1024 + col;
                split2(acc[mt][nt][half*2], acc[mt][nt][half*2 + 1], ctxh, ctxl, o);
            }
}

// ---------------- fused: time/pos add + ACT halt + layernorm1 -----------------
__global__ __launch_bounds__(256) void pre_layer(
    int t, const float* __restrict__ p_w, const float* __restrict__ p_b,
    const float* __restrict__ g, const float* __restrict__ bgm)
{
    __shared__ float sh1[8], sh2[8], sh3[8];
    int row = blockIdx.x;
    int l   = row & 511;
    int tid = threadIdx.x;
    float* x = g_state + (size_t)row * 1024;
    const float* ts = g_tsig + (size_t)l * 1024;
    const float* ps = g_psig + (size_t)t * 1024;
    float v[4];
    float sum = 0.f, dot = 0.f;
    #pragma unroll
    for (int j = 0; j < 4; j++) {
        int d = tid + 256*j;
        float sig = ts[d] + ps[d];
        float val = x[d] + sig;
        x[d] = val;
        v[j] = val;
        sum += val;
        dot += val * p_w[d];
    }
    #pragma unroll
    for (int o = 16; o; o >>= 1) {
        sum += __shfl_xor_sync(0xffffffffu, sum, o);
        dot += __shfl_xor_sync(0xffffffffu, dot, o);
    }
    if ((tid & 31) == 0) { sh1[tid >> 5] = sum; sh3[tid >> 5] = dot; }
    __syncthreads();
    float tot = 0.f, dtot = 0.f;
    #pragma unroll
    for (int w = 0; w < 8; w++) { tot += sh1[w]; dtot += sh3[w]; }
    float mu = tot * (1.f / 1024.f);
    float q = 0.f;
    #pragma unroll
    for (int j = 0; j < 4; j++) { float d = v[j] - mu; q += d * d; }
    #pragma unroll
    for (int o = 16; o; o >>= 1) q += __shfl_xor_sync(0xffffffffu, q, o);
    if ((tid & 31) == 0) sh2[tid >> 5] = q;
    __syncthreads();

    if (tid == 0) {
        float p   = 1.f / (1.f + expf(-(dtot + p_b[0])));
        float hp  = g_hp[row], rem = g_rem[row], nup = g_nup[row];
        float still = (hp < 1.0f) ? 1.f : 0.f;
        float add   = hp + p * still;
        float nh    = ((add > 0.9f) ? 1.f : 0.f) * still;
        still       = ((add <= 0.9f) ? 1.f : 0.f) * still;
        hp  += p * still;
        rem += nh * (1.f - hp);
        hp  += nh * rem;
        nup += still + nh;
        g_hp[row] = hp; g_rem[row] = rem; g_nup[row] = nup;
        g_uw[row] = p * still + nh * rem;
    }

    float qt = 0.f;
    #pragma unroll
    for (int w = 0; w < 8; w++) qt += sh2[w];
    float sd  = sqrtf(qt / 1023.f);
    float inv = 1.f / (sd + 1e-6f);
    #pragma unroll
    for (int j = 0; j < 4; j++) {
        int d = tid + 256*j;
        float y = g[d] * (v[j] - mu) * inv + bgm[d];
        bf16 h = __float2bfloat16(y);
        size_t o = (size_t)row * 1024 + d;
        g_xnh[o] = h;
        g_xnl[o] = __float2bfloat16(y - __bfloat162float(h));
    }
}

// ---------------- misc elementwise --------------------------------------------
__global__ void embed_init(const int* __restrict__ X, const float* __restrict__ emb) {
    int idx = blockIdx.x * 256 + threadIdx.x;
    int row = idx >> 10;
    int d   = idx & 1023;
    g_state[idx] = emb[(size_t)X[row] * 1024 + d];
    g_prev[idx]  = 0.f;
    if (idx < ROWS_) { g_hp[idx] = 0.f; g_rem[idx] = 0.f; g_nup[idx] = 0.f; }
}

// layernorm (fp32 in) -> bf16 hi/lo split outputs  (ln2)
__global__ __launch_bounds__(256) void layernorm_k(
    const float* __restrict__ in, bf16* __restrict__ ohi, bf16* __restrict__ olo,
    const float* __restrict__ g, const float* __restrict__ b)
{
    __shared__ float sh1[8], sh2[8];
    int row = blockIdx.x;
    int tid = threadIdx.x;
    const float* x = in + (size_t)row * 1024;
    float v[4];
    #pragma unroll
    for (int j = 0; j < 4; j++) v[j] = x[tid + 256*j];
    float s = v[0] + v[1] + v[2] + v[3];
    #pragma unroll
    for (int o = 16; o; o >>= 1) s += __shfl_xor_sync(0xffffffffu, s, o);
    if ((tid & 31) == 0) sh1[tid >> 5] = s;
    __syncthreads();
    float tot = 0.f;
    #pragma unroll
    for (int w = 0; w < 8; w++) tot += sh1[w];
    float mu = tot * (1.f / 1024.f);
    float q = 0.f;
    #pragma unroll
    for (int j = 0; j < 4; j++) { float d = v[j] - mu; q += d * d; }
    #pragma unroll
    for (int o = 16; o; o >>= 1) q += __shfl_xor_sync(0xffffffffu, q, o);
    if ((tid & 31) == 0) sh2[tid >> 5] = q;
    __syncthreads();
    float qt = 0.f;
    #pragma unroll
    for (int w = 0; w < 8; w++) qt += sh2[w];
    float sd  = sqrtf(qt / 1023.f);
    float inv = 1.f / (sd + 1e-6f);
    #pragma unroll
    for (int j = 0; j < 4; j++) {
        int d = tid + 256*j;
        float y = g[d] * (v[j] - mu) * inv + b[d];
        bf16 h = __float2bfloat16(y);
        size_t o = (size_t)row * 1024 + d;
        ohi[o] = h;
        olo[o] = __float2bfloat16(y - __bfloat162float(h));
    }
}

// ---------------- head (two-phase deterministic) -------------------------------
__global__ __launch_bounds__(256) void head_partial() {
    int b = blockIdx.x, c = blockIdx.y;
    int tid = threadIdx.x;
    float sum[4] = {0.f, 0.f, 0.f, 0.f};
    for (int l = c * 64; l < (c + 1) * 64; l++) {
        const float* p = g_prev + ((size_t)(b*512 + l)) * 1024;
        #pragma unroll
        for (int j = 0; j < 4; j++) sum[j] += p[tid + 256*j];
    }
    #pragma unroll
    for (int j = 0; j < 4; j++)
        g_hpart[((size_t)(b*8 + c)) * 1024 + tid + 256*j] = sum[j];
}

__global__ __launch_bounds__(256) void head_out(
    const float* __restrict__ W_out, const float* __restrict__ b_out, float* __restrict__ out)
{
    __shared__ float sh[4][256];
    int b = blockIdx.x;
    int tid = threadIdx.x;
    float sum[4] = {0.f, 0.f, 0.f, 0.f};
    for (int c = 0; c < 8; c++) {
        const float* p = g_hpart + ((size_t)(b*8 + c)) * 1024;
        #pragma unroll
        for (int j = 0; j < 4; j++) sum[j] += p[tid + 256*j];
    }
    float part[4] = {0.f, 0.f, 0.f, 0.f};
    #pragma unroll
    for (int j = 0; j < 4; j++) {
        int d = tid + 256*j;
        float m = sum[j] * (1.f / 512.f);
        #pragma unroll
        for (int o = 0; o < 4; o++) part[o] += m * W_out[d*4 + o];
    }
    #pragma unroll
    for (int o = 0; o < 4; o++) sh[o][tid] = part[o];
    __syncthreads();
    for (int s = 128; s > 0; s >>= 1) {
        if (tid < s)
            #pragma unroll
            for (int o = 0; o < 4; o++) sh[o][tid] += sh[o][tid + s];
        __syncthreads();
    }
    if (tid == 0) {
        float a[4];
        #pragma unroll
        for (int o = 0; o < 4; o++) { a[o] = sh[o][0] + b_out[o]; out[b*4 + o] = a[o]; }
        float mx = fmaxf(fmaxf(a[0], a[1]), fmaxf(a[2], a[3]));
        float e[4], s = 0.f;
        #pragma unroll
        for (int o = 0; o < 4; o++) { e[o] = expf(a[o] - mx); s += e[o]; }
        #pragma unroll
        for (int o = 0; o < 4; o++) out[32 + b*4 + o] = e[o] / s;
    }
}

__global__ void tail_out(float* __restrict__ out) {
    int i = blockIdx.x * 256 + threadIdx.x;
    out[64 + i]        = g_rem[i];
    out[64 + 4096 + i] = g_nup[i];
}

// ---------------- launcher ----------------------------------------------------
extern "C" void kernel_launch(void* const* d_in, const int* in_sizes, int n_in,
                              void* d_out, int out_size) {
    const int*   X     = (const int*)  d_in[0];
    const float* emb   = (const float*)d_in[1];
    const float* p_w   = (const float*)d_in[2];
    const float* p_b   = (const float*)d_in[3];
    const float* Wq    = (const float*)d_in[4];
    const float* Wk    = (const float*)d_in[5];
    const float* Wv    = (const float*)d_in[6];
    const float* Wo    = (const float*)d_in[7];
    const float* ln1_g = (const float*)d_in[8];
    const float* ln1_b = (const float*)d_in[9];
    const float* ln2_g = (const float*)d_in[10];
    const float* ln2_b = (const float*)d_in[11];
    const float* K1    = (const float*)d_in[12];
    const float* c1_b  = (const float*)d_in[13];
    const float* K2    = (const float*)d_in[14];
    const float* c2_b  = (const float*)d_in[15];
    const float* W_out = (const float*)d_in[16];
    const float* b_out = (const float*)d_in[17];
    float* out = (float*)d_out;

    float *state, *prevp, *uw;
    bf16 *xnh, *xnl, *qkvh, *qkvl, *vth, *vtl, *ctxh, *ctxl, *wh, *wl, *hh, *hl;
    bf16 *Wqkvh, *Wqkvl, *Woh, *Wol, *K1h, *K1l, *K2h, *K2l;
    cudaGetSymbolAddress((void**)&state, g_state);
    cudaGetSymbolAddress((void**)&prevp, g_prev);
    cudaGetSymbolAddress((void**)&uw,    g_uw);
    cudaGetSymbolAddress((void**)&xnh,   g_xnh);   cudaGetSymbolAddress((void**)&xnl,  g_xnl);
    cudaGetSymbolAddress((void**)&qkvh,  g_qkvh);  cudaGetSymbolAddress((void**)&qkvl, g_qkvl);
    cudaGetSymbolAddress((void**)&vth,   g_vth);   cudaGetSymbolAddress((void**)&vtl,  g_vtl);
    cudaGetSymbolAddress((void**)&ctxh,  g_ctxh);  cudaGetSymbolAddress((void**)&ctxl, g_ctxl);
    cudaGetSymbolAddress((void**)&wh,    g_wh);    cudaGetSymbolAddress((void**)&wl,   g_wl);
    cudaGetSymbolAddress((void**)&hh,    g_hh);    cudaGetSymbolAddress((void**)&hl,   g_hl);
    cudaGetSymbolAddress((void**)&Wqkvh, g_Wqkvh); cudaGetSymbolAddress((void**)&Wqkvl,g_Wqkvl);
    cudaGetSymbolAddress((void**)&Woh,   g_Woh);   cudaGetSymbolAddress((void**)&Wol,  g_Wol);
    cudaGetSymbolAddress((void**)&K1h,   g_K1h);   cudaGetSymbolAddress((void**)&K1l,  g_K1l);
    cudaGetSymbolAddress((void**)&K2h,   g_K2h);   cudaGetSymbolAddress((void**)&K2l,  g_K2l);

    cudaFuncSetAttribute(mm_gemm<0,0,1>,  cudaFuncAttributeMaxDynamicSharedMemorySize, SMEM_SZ);
    cudaFuncSetAttribute(mm_gemm<0,0,6>,  cudaFuncAttributeMaxDynamicSharedMemorySize, SMEM_SZ);
    cudaFuncSetAttribute(mm_gemm<1,10,2>, cudaFuncAttributeMaxDynamicSharedMemorySize, SMEM_SZ);
    cudaFuncSetAttribute(mm_gemm<1,12,5>, cudaFuncAttributeMaxDynamicSharedMemorySize, SMEM_SZ);
    cudaFuncSetAttribute(attn_fused, cudaFuncAttributeMaxDynamicSharedMemorySize, ASMEM);
    cudaFuncSetAttribute(attn_wv,    cudaFuncAttributeMaxDynamicSharedMemorySize, WSMEM);

    dim3 tb(32, 8);
    prep_square<<<dim3(32, 32, 4), tb>>>(Wq, Wk, Wv, Wo, Wqkvh, Wqkvl, Woh, Wol);
    prep_conv<<<24576, tb>>>(K1, K2, K1h, K1l, K2h, K2l);
    init_sig<<<518, 256>>>();
    embed_init<<<NST_/256, 256>>>(X, emb);

    for (int t = 0; t < NL_; t++) {
        pre_layer<<<ROWS_, 256>>>(t, p_w, p_b, ln1_g, ln1_b);

        mm_gemm<0,0,6><<<dim3(24, 32), 256, SMEM_SZ>>>(xnh, xnl, Wqkvh, Wqkvl,
            nullptr, qkvh, qkvl, nullptr, nullptr, nullptr, nullptr, 3*D_, D_);

        transpose_v<<<dim3(32, 16, 16), tb>>>(qkvh, qkvl, vth, vtl);

        attn_fused<<<dim3(16, 128), 256, ASMEM>>>(qkvh, qkvl, wh, wl);
        attn_wv<<<dim3(4, B_*H_), 256, WSMEM>>>(wh, wl, vth, vtl, ctxh, ctxl);

        dim3 gp(D_/128, ROWS_/128);
        mm_gemm<0,0,1><<<gp, 256, SMEM_SZ>>>(ctxh, ctxl, Woh, Wol,
            state, nullptr, nullptr, state, nullptr, nullptr, nullptr, D_, D_);
        layernorm_k<<<ROWS_, 256>>>(state, xnh, xnl, ln2_g, ln2_b);

        mm_gemm<1,10,2><<<dim3(F_/128, ROWS_/128), 256, SMEM_SZ>>>(xnh, xnl, K1h, K1l,
            nullptr, hh, hl, nullptr, c1_b, nullptr, nullptr, F_, 3*D_);
        mm_gemm<1,12,5><<<gp, 256, SMEM_SZ>>>(hh, hl, K2h, K2l,
            state, nullptr, nullptr, state, c2_b, uw, prevp, D_, 3*F_);
    }

    head_partial<<<dim3(8, 8), 256>>>();
    head_out<<<B_, 256>>>(W_out, b_out, out);
    tail_out<<<ROWS_/256, 256>>>(out);
}

// round 17
// speedup vs baseline: 1.1165x; 1.0062x over previous
#include <cuda_runtime.h>
#include <cuda_bf16.h>
#include <cstdint>
#include <math.h>

#define B_    8
#define L_    512
#define D_    1024
#define H_    16
#define F_    4096
#define NL_   6
#define ROWS_ (B_*L_)          /* 4096 */
#define NST_  (ROWS_*D_)       /* 4194304 */

typedef __nv_bfloat16 bf16;

// ---------------- scratch (device globals; no allocation allowed) ------------
__device__ float g_state[NST_];
__device__ float g_prev [NST_];

__device__ bf16 g_xnh[NST_],  g_xnl[NST_];
__device__ bf16 g_qkvh[(size_t)ROWS_*3*D_], g_qkvl[(size_t)ROWS_*3*D_];
__device__ bf16 g_vth[NST_],  g_vtl[NST_];
__device__ bf16 g_ctxh[NST_], g_ctxl[NST_];
__device__ bf16 g_wh[(size_t)B_*H_*L_*L_], g_wl[(size_t)B_*H_*L_*L_];
__device__ bf16 g_hh[(size_t)ROWS_*F_], g_hl[(size_t)ROWS_*F_];

// transposed+split weights [N][K]
__device__ bf16 g_Wqkvh[3*D_*D_], g_Wqkvl[3*D_*D_];
__device__ bf16 g_Woh[D_*D_], g_Wol[D_*D_];
__device__ bf16 g_K1h[(size_t)F_*3*D_], g_K1l[(size_t)F_*3*D_];
__device__ bf16 g_K2h[(size_t)D_*3*F_], g_K2l[(size_t)D_*3*F_];

__device__ float g_hp [ROWS_];
__device__ float g_rem[ROWS_];
__device__ float g_nup[ROWS_];
__device__ float g_uw [ROWS_];

// precomputed timing/positional signals + head partials
__device__ float g_tsig[512*1024];
__device__ float g_psig[NL_*1024];
__device__ float g_hpart[64*1024];

// ---------------- PTX helpers -------------------------------------------------
__device__ __forceinline__ uint32_t smem_u32(const void* p) {
    uint32_t a;
    asm("{ .reg .u64 t; cvta.to.shared.u64 t, %1; cvt.u32.u64 %0, t; }" : "=r"(a) : "l"(p));
    return a;
}
__device__ __forceinline__ void cpa16(uint32_t dst, const void* src, int sz) {
    asm volatile("cp.async.cg.shared.global [%0], [%1], 16, %2;" :: "r"(dst), "l"(src), "r"(sz));
}
__device__ __forceinline__ void ldm4(uint32_t* r, uint32_t addr) {
    asm volatile("ldmatrix.sync.aligned.m8n8.x4.shared.b16 {%0,%1,%2,%3}, [%4];"
        : "=r"(r[0]), "=r"(r[1]), "=r"(r[2]), "=r"(r[3]) : "r"(addr));
}
__device__ __forceinline__ void mma16816(float* c, const uint32_t* a, uint32_t b0, uint32_t b1) {
    asm volatile("mma.sync.aligned.m16n8k16.row.col.f32.bf16.bf16.f32 "
        "{%0,%1,%2,%3}, {%4,%5,%6,%7}, {%8,%9}, {%0,%1,%2,%3};"
        : "+f"(c[0]), "+f"(c[1]), "+f"(c[2]), "+f"(c[3])
        : "r"(a[0]), "r"(a[1]), "r"(a[2]), "r"(a[3]), "r"(b0), "r"(b1));
}
__device__ __forceinline__ void split2(float v0, float v1, bf16* hi, bf16* lo, size_t o) {
    bf16 h0 = __float2bfloat16(v0), h1 = __float2bfloat16(v1);
    __nv_bfloat162 hh2; hh2.x = h0; hh2.y = h1;
    *(__nv_bfloat162*)(hi + o) = hh2;
    __nv_bfloat162 ll2;
    ll2.x = __float2bfloat16(v0 - __bfloat162float(h0));
    ll2.y = __float2bfloat16(v1 - __bfloat162float(h1));
    *(__nv_bfloat162*)(lo + o) = ll2;
}

// ---------------- weight transpose + bf16 split ------------------------------
__device__ __forceinline__ void tsplit_body(const float* __restrict__ in, int inRowLen,
                                            bf16* __restrict__ ohi, bf16* __restrict__ olo,
                                            int outStride, int n0, int k0)
{
    __shared__ float t[32][33];
    int tx = threadIdx.x, ty = threadIdx.y;
    #pragma unroll
    for (int i = 0; i < 32; i += 8)
        t[ty + i][tx] = in[(size_t)(k0 + ty + i) * inRowLen + n0 + tx];
    __syncthreads();
    #pragma unroll
    for (int i = 0; i < 32; i += 8) {
        float v = t[tx][ty + i];
        bf16 h = __float2bfloat16(v);
        size_t o = (size_t)(n0 + ty + i) * outStride + k0 + tx;
        ohi[o] = h;
        olo[o] = __float2bfloat16(v - __bfloat162float(h));
    }
}

__global__ void prep_square(const float* __restrict__ Wq, const float* __restrict__ Wk,
                            const float* __restrict__ Wv, const float* __restrict__ Wo,
                            bf16* __restrict__ Wqkvh, bf16* __restrict__ Wqkvl,
                            bf16* __restrict__ Woh, bf16* __restrict__ Wol)
{
    int z = blockIdx.z;
    const float* in = (z == 0) ? Wq : (z == 1) ? Wk : (z == 2) ? Wv : Wo;
    bf16* oh = (z == 3) ? Woh : (Wqkvh + (size_t)z * 1024 * 1024);
    bf16* ol = (z == 3) ? Wol : (Wqkvl + (size_t)z * 1024 * 1024);
    tsplit_body(in, 1024, oh, ol, 1024, blockIdx.x * 32, blockIdx.y * 32);
}

__global__ void prep_conv(const float* __restrict__ K1, const float* __restrict__ K2,
                          bf16* __restrict__ K1h, bf16* __restrict__ K1l,
                          bf16* __restrict__ K2h, bf16* __restrict__ K2l)
{
    int id = blockIdx.x;
    if (id < 12288) {
        int w = id / 4096, r = id % 4096;
        int n0 = (r % 128) * 32, k0 = (r / 128) * 32;
        tsplit_body(K1 + (size_t)w * 1024 * 4096, 4096,
                    K1h + (size_t)w * 1024, K1l + (size_t)w * 1024, 3072, n0, k0);
    } else {
        id -= 12288;
        int w = id / 4096, r = id % 4096;
        int n0 = (r % 32) * 32, k0 = (r / 32) * 32;
        tsplit_body(K2 + (size_t)w * 4096 * 1024, 1024,
                    K2h + (size_t)w * 4096, K2l + (size_t)w * 4096, 12288, n0, k0);
    }
}

// precompute time/pos signals
__global__ void init_sig() {
    const float NEG_LOG_INC = -0.018024149455921103f;  // -ln(10000)/511
    int r = blockIdx.x;
    int tid = threadIdx.x;
    #pragma unroll
    for (int j = 0; j < 4; j++) {
        int d = tid + 256*j;
        int i = d & 511;
        float invt = expf((float)i * NEG_LOG_INC);
        if (r < 512) {
            float a = (float)r * invt;
            g_tsig[r*1024 + d] = (d < 512) ? sinf(a) : cosf(a);
        } else {
            int t = r - 512;
            float a = (float)t * invt;
            g_psig[t*1024 + d] = (d < 512) ? sinf(a) : cosf(a);
        }
    }
}

// ---------------- mma.sync GEMM (128x128 tile, 2-stage, occ 2) ----------------
// EPI 1: Cf = acc+res (Wo)
// EPI 2: split(relu(acc+bias)) (conv1)
// EPI 5: Cf = acc+bias+res; prev = Cf*uw + prev*(1-uw)  (conv2 + prev_update)
// EPI 6: fused QKV: cols<1024 q-scaled split -> Chi/Clo; cols 1024..2047 split
//        -> Chi/Clo; cols>=2048 (V) split written TRANSPOSED -> Vth/Vtl
#define TSTR    40
#define TBYTES  (128*TSTR*2)       /* 10240 */
#define STAGE_B (4*TBYTES)         /* 40960 */
#define SMEM_SZ (2*STAGE_B)        /* 81920 */

__device__ __forceinline__ void ld_plain(const bf16* __restrict__ src, int row0, int K,
                                         int k0, uint32_t sbase, int tid)
{
    #pragma unroll
    for (int i = 0; i < 2; i++) {
        int unit = i * 256 + tid;
        int row = unit >> 2, ch = unit & 3;
        cpa16(sbase + row * (TSTR*2) + ch * 16,
              src + (size_t)(row0 + row) * K + k0 + ch * 8, 16);
    }
}

template<int DSHIFT>
__device__ __forceinline__ void ld_conv(const bf16* __restrict__ src, int bm,
                                        int k0, uint32_t sbase, int tid)
{
    int w  = k0 >> DSHIFT;
    int cb = k0 & ((1 << DSHIFT) - 1);
    #pragma unroll
    for (int i = 0; i < 2; i++) {
        int unit = i * 256 + tid;
        int row = unit >> 2, ch = unit & 3;
        int r = bm + row;
        int b = r >> 9;
        int l = (r & 511) + w - 1;
        int ok = ((unsigned)l < 512u);
        int lc = ok ? l : 0;
        cpa16(sbase + row * (TSTR*2) + ch * 16,
              src + (((size_t)(b * 512 + lc)) << DSHIFT) + cb + ch * 8, ok ? 16 : 0);
    }
}

template<int CONV, int DSHIFT>
__device__ __forceinline__ void ld_stage(const bf16* __restrict__ Ahi, const bf16* __restrict__ Alo,
                                         const bf16* __restrict__ Bhi, const bf16* __restrict__ Blo,
                                         int bm, int bn, int K, int k0, uint32_t s, int tid)
{
    if (CONV) { ld_conv<DSHIFT>(Ahi, bm, k0, s, tid); ld_conv<DSHIFT>(Alo, bm, k0, s + TBYTES, tid); }
    else      { ld_plain(Ahi, bm, K, k0, s, tid);      ld_plain(Alo, bm, K, k0, s + TBYTES, tid); }
    ld_plain(Bhi, bn, K, k0, s + 2*TBYTES, tid);
    ld_plain(Blo, bn, K, k0, s + 3*TBYTES, tid);
}

template<int CONV, int DSHIFT, int EPI>
__global__ __launch_bounds__(256, 2)
void mm_gemm(const bf16* __restrict__ Ahi, const bf16* __restrict__ Alo,
             const bf16* __restrict__ Bhi, const bf16* __restrict__ Blo,
             float* __restrict__ Cf, bf16* __restrict__ Chi, bf16* __restrict__ Clo,
             const float* __restrict__ res, const float* __restrict__ bias,
             const float* __restrict__ uw, float* __restrict__ prevp,
             bf16* __restrict__ Vth, bf16* __restrict__ Vtl,
             int Nglob, int K)
{
    extern __shared__ char smem[];
    uint32_t sb = smem_u32(smem);
    int tid = threadIdx.x, wid = tid >> 5, lane = tid & 31;
    int bm = blockIdx.y * 128, bn = blockIdx.x * 128;
    int wm = wid & 3, wn = wid >> 2;

    float acc[2][8][4];
    #pragma unroll
    for (int mt = 0; mt < 2; mt++)
        #pragma unroll
        for (int nt = 0; nt < 8; nt++)
            #pragma unroll
            for (int j = 0; j < 4; j++) acc[mt][nt][j] = 0.f;

    int nch = K >> 5;

    ld_stage<CONV,DSHIFT>(Ahi, Alo, Bhi, Blo, bm, bn, K, 0, sb, tid);
    asm volatile("cp.async.commit_group;");

    for (int i = 0; i < nch; i++) {
        asm volatile("cp.async.wait_group 0;");
        __syncthreads();
        if (i + 1 < nch) {
            ld_stage<CONV,DSHIFT>(Ahi, Alo, Bhi, Blo, bm, bn, K, (i + 1) << 5,
                                  sb + ((i + 1) & 1) * STAGE_B, tid);
            asm volatile("cp.async.commit_group;");
        }

        uint32_t s = sb + (i & 1) * STAGE_B;
        #pragma unroll
        for (int ks = 0; ks < 2; ks++) {
            uint32_t ah[2][4], al[2][4];
            #pragma unroll
            for (int mt = 0; mt < 2; mt++) {
                uint32_t ra = s + (uint32_t)((wm*32 + mt*16) + (lane & 15)) * (TSTR*2)
                            + ks * 32 + (lane >> 4) * 16;
                ldm4(ah[mt], ra);
                ldm4(al[mt], ra + TBYTES);
            }
            uint32_t bh[4][4], bl[4][4];
            #pragma unroll
            for (int g = 0; g < 4; g++) {
                uint32_t rb = s + 2*TBYTES + (uint32_t)((wn*64 + g*16) + (lane & 15)) * (TSTR*2)
                            + ks * 32 + (lane >> 4) * 16;
                ldm4(bh[g], rb);
                ldm4(bl[g], rb + TBYTES);
            }
            #pragma unroll
            for (int mt = 0; mt < 2; mt++)
                #pragma unroll
                for (int nt = 0; nt < 8; nt++) {
                    int g = nt >> 1, o = nt & 1;
                    mma16816(acc[mt][nt], ah[mt], bh[g][o], bh[g][o + 2]);
                    mma16816(acc[mt][nt], ah[mt], bl[g][o], bl[g][o + 2]);
                    mma16816(acc[mt][nt], al[mt], bh[g][o], bh[g][o + 2]);
                }
        }
    }

    #pragma unroll
    for (int mt = 0; mt < 2; mt++)
        #pragma unroll
        for (int nt = 0; nt < 8; nt++)
            #pragma unroll
            for (int half = 0; half < 2; half++) {
                int row = bm + wm*32 + mt*16 + (lane >> 2) + half*8;
                int col = bn + wn*64 + nt*8 + (lane & 3)*2;
                float v0 = acc[mt][nt][half*2 + 0];
                float v1 = acc[mt][nt][half*2 + 1];
                size_t o = (size_t)row * Nglob + col;
                if (EPI == 1) {
                    float2 rr = *(const float2*)(res + o);
                    *(float2*)(Cf + o) = make_float2(v0 + rr.x, v1 + rr.y);
                } else if (EPI == 2) {
                    float2 bb = *(const float2*)(bias + col);
                    v0 = fmaxf(v0 + bb.x, 0.f);
                    v1 = fmaxf(v1 + bb.y, 0.f);
                    split2(v0, v1, Chi, Clo, o);
                } else if (EPI == 5) {
                    float2 rr = *(const float2*)(res + o);
                    float2 bb = *(const float2*)(bias + col);
                    float s0 = v0 + bb.x + rr.x;
                    float s1 = v1 + bb.y + rr.y;
                    *(float2*)(Cf + o) = make_float2(s0, s1);
                    float u = uw[row];
                    float2 pv = *(const float2*)(prevp + o);
                    *(float2*)(prevp + o) = make_float2(s0 * u + pv.x * (1.f - u),
                                                        s1 * u + pv.y * (1.f - u));
                } else {  // EPI 6
                    if (col < 2048) {
                        float a = (col < 1024) ? 0.125f : 1.0f;
                        split2(v0 * a, v1 * a, Chi, Clo, o);
                    } else {
                        // V part: write transposed directly into vt[(b*1024+c)*512+l]
                        int c  = col - 2048;
                        int bb = row >> 9;
                        int l  = row & 511;
                        size_t o1 = ((size_t)(bb * 1024 + c)) * 512 + l;
                        size_t o2 = o1 + 512;
                        bf16 h0 = __float2bfloat16(v0), h1 = __float2bfloat16(v1);
                        Vth[o1] = h0;
                        Vth[o2] = h1;
                        Vtl[o1] = __float2bfloat16(v0 - __bfloat162float(h0));
                        Vtl[o2] = __float2bfloat16(v1 - __bfloat162float(h1));
                    }
                }
            }
}

// ---------------- fused attention: logits + softmax -> prob hi/lo -------------
#define AQ_STR 72
#define AQ_TB  (32*AQ_STR*2)    /* 4608 */
#define AK_TB  (128*AQ_STR*2)   /* 18432 */
#define ASMEM  (2*AQ_TB + 2*AK_TB)  /* 46080 */

__global__ __launch_bounds__(256, 2)
void attn_fused(const bf16* __restrict__ qkvh, const bf16* __restrict__ qkvl,
                bf16* __restrict__ wh, bf16* __restrict__ wl)
{
    extern __shared__ char smem[];
    __shared__ float sredM[8][32];
    __shared__ float sredS[8][32];
    uint32_t sb = smem_u32(smem);
    int tid = threadIdx.x, wid = tid >> 5, lane = tid & 31;
    int bz = blockIdx.y;
    int b = bz >> 4, h = bz & 15;
    int q0 = blockIdx.x * 32;
    uint32_t ksm = sb + 2*AQ_TB;

    {
        int row = tid >> 3, ch = tid & 7;
        uint32_t d = (uint32_t)(row * (AQ_STR*2) + ch * 16);
        size_t so = ((size_t)(b*512 + q0 + row)) * 3072 + h*64 + ch*8;
        cpa16(sb + d,         qkvh + so, 16);
        cpa16(sb + AQ_TB + d, qkvl + so, 16);
    }
    asm volatile("cp.async.commit_group;");

    float acc[2][8][4];
    #pragma unroll
    for (int mt = 0; mt < 2; mt++)
        #pragma unroll
        for (int g = 0; g < 8; g++)
            #pragma unroll
            for (int j = 0; j < 4; j++) acc[mt][g][j] = 0.f;

    for (int c = 0; c < 4; c++) {
        #pragma unroll
        for (int i = 0; i < 4; i++) {
            int unit = i * 256 + tid;
            int row = unit >> 3, ch = unit & 7;
            uint32_t d = (uint32_t)(row * (AQ_STR*2) + ch * 16);
            size_t so = ((size_t)(b*512 + c*128 + row)) * 3072 + 1024 + h*64 + ch*8;
            cpa16(ksm + d,         qkvh + so, 16);
            cpa16(ksm + AK_TB + d, qkvl + so, 16);
        }
        asm volatile("cp.async.commit_group;");
        asm volatile("cp.async.wait_group 0;");
        __syncthreads();

        #pragma unroll
        for (int ks = 0; ks < 4; ks++) {
            uint32_t ah[2][4], al[2][4];
            #pragma unroll
            for (int mt = 0; mt < 2; mt++) {
                uint32_t ra = sb + (uint32_t)((mt*16 + (lane & 15)) * (AQ_STR*2))
                            + ks * 32 + (lane >> 4) * 16;
                ldm4(ah[mt], ra);
                ldm4(al[mt], ra + AQ_TB);
            }
            uint32_t bh4[4], bl4[4];
            int rowb = ((lane & 8) ? 64 : 0) + wid*8 + (lane & 7);
            uint32_t rb = ksm + (uint32_t)(rowb * (AQ_STR*2)) + ks * 32 + (lane >> 4) * 16;
            ldm4(bh4, rb);
            ldm4(bl4, rb + AK_TB);
            #pragma unroll
            for (int mt = 0; mt < 2; mt++)
                #pragma unroll
                for (int j = 0; j < 2; j++) {
                    int g = 2*c + j;
                    mma16816(acc[mt][g], ah[mt], bh4[j], bh4[j + 2]);
                    mma16816(acc[mt][g], ah[mt], bl4[j], bl4[j + 2]);
                    mma16816(acc[mt][g], al[mt], bh4[j], bh4[j + 2]);
                }
        }
        __syncthreads();
    }

    #pragma unroll
    for (int mt = 0; mt < 2; mt++)
        #pragma unroll
        for (int hf = 0; hf < 2; hf++) {
            float m = -1e30f;
            #pragma unroll
            for (int g = 0; g < 8; g++) {
                m = fmaxf(m, acc[mt][g][hf*2 + 0]);
                m = fmaxf(m, acc[mt][g][hf*2 + 1]);
            }
            m = fmaxf(m, __shfl_xor_sync(0xffffffffu, m, 1));
            m = fmaxf(m, __shfl_xor_sync(0xffffffffu, m, 2));
            if ((lane & 3) == 0) sredM[wid][mt*16 + (lane >> 2) + hf*8] = m;
        }
    __syncthreads();
    #pragma unroll
    for (int mt = 0; mt < 2; mt++)
        #pragma unroll
        for (int hf = 0; hf < 2; hf++) {
            int r = mt*16 + (lane >> 2) + hf*8;
            float m = sredM[0][r];
            #pragma unroll
            for (int w = 1; w < 8; w++) m = fmaxf(m, sredM[w][r]);
            float s = 0.f;
            #pragma unroll
            for (int g = 0; g < 8; g++) {
                float e0 = expf(acc[mt][g][hf*2 + 0] - m);
                float e1 = expf(acc[mt][g][hf*2 + 1] - m);
                acc[mt][g][hf*2 + 0] = e0;
                acc[mt][g][hf*2 + 1] = e1;
                s += e0 + e1;
            }
            s += __shfl_xor_sync(0xffffffffu, s, 1);
            s += __shfl_xor_sync(0xffffffffu, s, 2);
            if ((lane & 3) == 0) sredS[wid][r] = s;
        }
    __syncthreads();
    #pragma unroll
    for (int mt = 0; mt < 2; mt++)
        #pragma unroll
        for (int hf = 0; hf < 2; hf++) {
            int r = mt*16 + (lane >> 2) + hf*8;
            float s = 0.f;
            #pragma unroll
            for (int w = 0; w < 8; w++) s += sredS[w][r];
            float inv = 1.f / s;
            size_t rowo = ((size_t)bz*512 + q0 + r) * 512;
            #pragma unroll
            for (int g = 0; g < 8; g++) {
                size_t o = rowo + g*64 + wid*8 + (lane & 3)*2;
                split2(acc[mt][g][hf*2 + 0] * inv, acc[mt][g][hf*2 + 1] * inv, wh, wl, o);
            }
        }
}

// ---------------- attention: ctx = w@v (per bh), tile 128x64, K=512 -----------
#define WA_B  (128*TSTR*2)   /* 10240 */
#define WB_B  (64*TSTR*2)    /* 5120 */
#define WSTAGE (2*WA_B + 2*WB_B)   /* 30720 */
#define WSMEM (2*WSTAGE)           /* 61440 */

__global__ __launch_bounds__(256, 2)
void attn_wv(const bf16* __restrict__ wh, const bf16* __restrict__ wl,
             const bf16* __restrict__ vth, const bf16* __restrict__ vtl,
             bf16* __restrict__ ctxh, bf16* __restrict__ ctxl)
{
    extern __shared__ char smem[];
    uint32_t sb = smem_u32(smem);
    int tid = threadIdx.x, wid = tid >> 5, lane = tid & 31;
    int bz = blockIdx.y;
    int b = bz >> 4, h = bz & 15;
    size_t abase = (size_t)bz*262144 + (size_t)blockIdx.x*65536;
    size_t bbase = (size_t)bz*32768;
    int wm = wid & 3, wn = wid >> 2;

    float acc[2][4][4];
    #pragma unroll
    for (int mt = 0; mt < 2; mt++)
        #pragma unroll
        for (int nt = 0; nt < 4; nt++)
            #pragma unroll
            for (int j = 0; j < 4; j++) acc[mt][nt][j] = 0.f;

    auto load_chunk = [&](int k0, uint32_t s) {
        #pragma unroll
        for (int i = 0; i < 2; i++) {
            int unit = i * 256 + tid;
            int row = unit >> 2, ch = unit & 3;
            uint32_t d = (uint32_t)(row * (TSTR*2) + ch * 16);
            size_t so = abase + (size_t)row * 512 + k0 + ch * 8;
            cpa16(s + d,        wh + so, 16);
            cpa16(s + WA_B + d, wl + so, 16);
        }
        {
            int row = tid >> 2, ch = tid & 3;
            uint32_t d = (uint32_t)(row * (TSTR*2) + ch * 16);
            size_t so = bbase + (size_t)row * 512 + k0 + ch * 8;
            cpa16(s + 2*WA_B + d,        vth + so, 16);
            cpa16(s + 2*WA_B + WB_B + d, vtl + so, 16);
        }
    };

    load_chunk(0, sb);
    asm volatile("cp.async.commit_group;");

    for (int i = 0; i < 16; i++) {
        asm volatile("cp.async.wait_group 0;");
        __syncthreads();
        if (i + 1 < 16) {
            load_chunk((i + 1) << 5, sb + ((i + 1) & 1) * WSTAGE);
            asm volatile("cp.async.commit_group;");
        }

        uint32_t s = sb + (i & 1) * WSTAGE;
        #pragma unroll
        for (int ks = 0; ks < 2; ks++) {
            uint32_t ah[2][4], al[2][4];
            #pragma unroll
            for (int mt = 0; mt < 2; mt++) {
                uint32_t ra = s + (uint32_t)((wm*32 + mt*16) + (lane & 15)) * (TSTR*2)
                            + ks * 32 + (lane >> 4) * 16;
                ldm4(ah[mt], ra);
                ldm4(al[mt], ra + WA_B);
            }
            uint32_t bh[2][4], bl[2][4];
            #pragma unroll
            for (int g = 0; g < 2; g++) {
                uint32_t rb = s + 2*WA_B + (uint32_t)((wn*32 + g*16) + (lane & 15)) * (TSTR*2)
                            + ks * 32 + (lane >> 4) * 16;
                ldm4(bh[g], rb);
                ldm4(bl[g], rb + WB_B);
            }
            #pragma unroll
            for (int mt = 0; mt < 2; mt++)
                #pragma unroll
                for (int nt = 0; nt < 4; nt++) {
                    int g = nt >> 1, o = nt & 1;
                    mma16816(acc[mt][nt], ah[mt], bh[g][o], bh[g][o + 2]);
                    mma16816(acc[mt][nt], ah[mt], bl[g][o], bl[g][o + 2]);
                    mma16816(acc[mt][nt], al[mt], bh[g][o], bh[g][o + 2]);
                }
        }
    }

    #pragma unroll
    for (int mt = 0; mt < 2; mt++)
        #pragma unroll
        for (int nt = 0; nt < 4; nt++)
            #pragma unroll
            for (int half = 0; half < 2; half++) {
                int rloc = wm*32 + mt*16 + (lane >> 2) + half*8;
                int row = b*512 + blockIdx.x*128 + rloc;
                int col = h*64 + wn*32 + nt*8 + (lane & 3)*2;
                size_t o = (size_t)row * 1024 + col;
                split2(acc[mt][nt][half*2], acc[mt][nt][half*2 + 1], ctxh, ctxl, o);
            }
}

// ---------------- fused: time/pos add + ACT halt + layernorm1 -----------------
__global__ __launch_bounds__(256) void pre_layer(
    int t, const float* __restrict__ p_w, const float* __restrict__ p_b,
    const float* __restrict__ g, const float* __restrict__ bgm)
{
    __shared__ float sh1[8], sh2[8], sh3[8];
    int row = blockIdx.x;
    int l   = row & 511;
    int tid = threadIdx.x;
    float* x = g_state + (size_t)row * 1024;
    const float* ts = g_tsig + (size_t)l * 1024;
    const float* ps = g_psig + (size_t)t * 1024;
    float v[4];
    float sum = 0.f, dot = 0.f;
    #pragma unroll
    for (int j = 0; j < 4; j++) {
        int d = tid + 256*j;
        float sig = ts[d] + ps[d];
        float val = x[d] + sig;
        x[d] = val;
        v[j] = val;
        sum += val;
        dot += val * p_w[d];
    }
    #pragma unroll
    for (int o = 16; o; o >>= 1) {
        sum += __shfl_xor_sync(0xffffffffu, sum, o);
        dot += __shfl_xor_sync(0xffffffffu, dot, o);
    }
    if ((tid & 31) == 0) { sh1[tid >> 5] = sum; sh3[tid >> 5] = dot; }
    __syncthreads();
    float tot = 0.f, dtot = 0.f;
    #pragma unroll
    for (int w = 0; w < 8; w++) { tot += sh1[w]; dtot += sh3[w]; }
    float mu = tot * (1.f / 1024.f);
    float q = 0.f;
    #pragma unroll
    for (int j = 0; j < 4; j++) { float d = v[j] - mu; q += d * d; }
    #pragma unroll
    for (int o = 16; o; o >>= 1) q += __shfl_xor_sync(0xffffffffu, q, o);
    if ((tid & 31) == 0) sh2[tid >> 5] = q;
    __syncthreads();

    if (tid == 0) {
        float p   = 1.f / (1.f + expf(-(dtot + p_b[0])));
        float hp  = g_hp[row], rem = g_rem[row], nup = g_nup[row];
        float still = (hp < 1.0f) ? 1.f : 0.f;
        float add   = hp + p * still;
        float nh    = ((add > 0.9f) ? 1.f : 0.f) * still;
        still       = ((add <= 0.9f) ? 1.f : 0.f) * still;
        hp  += p * still;
        rem += nh * (1.f - hp);
        hp  += nh * rem;
        nup += still + nh;
        g_hp[row] = hp; g_rem[row] = rem; g_nup[row] = nup;
        g_uw[row] = p * still + nh * rem;
    }

    float qt = 0.f;
    #pragma unroll
    for (int w = 0; w < 8; w++) qt += sh2[w];
    float sd  = sqrtf(qt / 1023.f);
    float inv = 1.f / (sd + 1e-6f);
    #pragma unroll
    for (int j = 0; j < 4; j++) {
        int d = tid + 256*j;
        float y = g[d] * (v[j] - mu) * inv + bgm[d];
        bf16 h = __float2bfloat16(y);
        size_t o = (size_t)row * 1024 + d;
        g_xnh[o] = h;
        g_xnl[o] = __float2bfloat16(y - __bfloat162float(h));
    }
}

// ---------------- misc elementwise --------------------------------------------
__global__ void embed_init(const int* __restrict__ X, const float* __restrict__ emb) {
    int idx = blockIdx.x * 256 + threadIdx.x;
    int row = idx >> 10;
    int d   = idx & 1023;
    g_state[idx] = emb[(size_t)X[row] * 1024 + d];
    g_prev[idx]  = 0.f;
    if (idx < ROWS_) { g_hp[idx] = 0.f; g_rem[idx] = 0.f; g_nup[idx] = 0.f; }
}

// layernorm (fp32 in) -> bf16 hi/lo split outputs  (ln2)
__global__ __launch_bounds__(256) void layernorm_k(
    const float* __restrict__ in, bf16* __restrict__ ohi, bf16* __restrict__ olo,
    const float* __restrict__ g, const float* __restrict__ b)
{
    __shared__ float sh1[8], sh2[8];
    int row = blockIdx.x;
    int tid = threadIdx.x;
    const float* x = in + (size_t)row * 1024;
    float v[4];
    #pragma unroll
    for (int j = 0; j < 4; j++) v[j] = x[tid + 256*j];
    float s = v[0] + v[1] + v[2] + v[3];
    #pragma unroll
    for (int o = 16; o; o >>= 1) s += __shfl_xor_sync(0xffffffffu, s, o);
    if ((tid & 31) == 0) sh1[tid >> 5] = s;
    __syncthreads();
    float tot = 0.f;
    #pragma unroll
    for (int w = 0; w < 8; w++) tot += sh1[w];
    float mu = tot * (1.f / 1024.f);
    float q = 0.f;
    #pragma unroll
    for (int j = 0; j < 4; j++) { float d = v[j] - mu; q += d * d; }
    #pragma unroll
    for (int o = 16; o; o >>= 1) q += __shfl_xor_sync(0xffffffffu, q, o);
    if ((tid & 31) == 0) sh2[tid >> 5] = q;
    __syncthreads();
    float qt = 0.f;
    #pragma unroll
    for (int w = 0; w < 8; w++) qt += sh2[w];
    float sd  = sqrtf(qt / 1023.f);
    float inv = 1.f / (sd + 1e-6f);
    #pragma unroll
    for (int j = 0; j < 4; j++) {
        int d = tid + 256*j;
        float y = g[d] * (v[j] - mu) * inv + b[d];
        bf16 h = __float2bfloat16(y);
        size_t o = (size_t)row * 1024 + d;
        ohi[o] = h;
        olo[o] = __float2bfloat16(y - __bfloat162float(h));
    }
}

// ---------------- head (two-phase deterministic) -------------------------------
__global__ __launch_bounds__(256) void head_partial() {
    int b = blockIdx.x, c = blockIdx.y;
    int tid = threadIdx.x;
    float sum[4] = {0.f, 0.f, 0.f, 0.f};
    for (int l = c * 64; l < (c + 1) * 64; l++) {
        const float* p = g_prev + ((size_t)(b*512 + l)) * 1024;
        #pragma unroll
        for (int j = 0; j < 4; j++) sum[j] += p[tid + 256*j];
    }
    #pragma unroll
    for (int j = 0; j < 4; j++)
        g_hpart[((size_t)(b*8 + c)) * 1024 + tid + 256*j] = sum[j];
}

__global__ __launch_bounds__(256) void head_out(
    const float* __restrict__ W_out, const float* __restrict__ b_out, float* __restrict__ out)
{
    __shared__ float sh[4][256];
    int b = blockIdx.x;
    int tid = threadIdx.x;
    float sum[4] = {0.f, 0.f, 0.f, 0.f};
    for (int c = 0; c < 8; c++) {
        const float* p = g_hpart + ((size_t)(b*8 + c)) * 1024;
        #pragma unroll
        for (int j = 0; j < 4; j++) sum[j] += p[tid + 256*j];
    }
    float part[4] = {0.f, 0.f, 0.f, 0.f};
    #pragma unroll
    for (int j = 0; j < 4; j++) {
        int d = tid + 256*j;
        float m = sum[j] * (1.f / 512.f);
        #pragma unroll
        for (int o = 0; o < 4; o++) part[o] += m * W_out[d*4 + o];
    }
    #pragma unroll
    for (int o = 0; o < 4; o++) sh[o][tid] = part[o];
    __syncthreads();
    for (int s = 128; s > 0; s >>= 1) {
        if (tid < s)
            #pragma unroll
            for (int o = 0; o < 4; o++) sh[o][tid] += sh[o][tid + s];
        __syncthreads();
    }
    if (tid == 0) {
        float a[4];
        #pragma unroll
        for (int o = 0; o < 4; o++) { a[o] = sh[o][0] + b_out[o]; out[b*4 + o] = a[o]; }
        float mx = fmaxf(fmaxf(a[0], a[1]), fmaxf(a[2], a[3]));
        float e[4], s = 0.f;
        #pragma unroll
        for (int o = 0; o < 4; o++) { e[o] = expf(a[o] - mx); s += e[o]; }
        #pragma unroll
        for (int o = 0; o < 4; o++) out[32 + b*4 + o] = e[o] / s;
    }
}

__global__ void tail_out(float* __restrict__ out) {
    int i = blockIdx.x * 256 + threadIdx.x;
    out[64 + i]        = g_rem[i];
    out[64 + 4096 + i] = g_nup[i];
}

// ---------------- launcher ----------------------------------------------------
extern "C" void kernel_launch(void* const* d_in, const int* in_sizes, int n_in,
                              void* d_out, int out_size) {
    const int*   X     = (const int*)  d_in[0];
    const float* emb   = (const float*)d_in[1];
    const float* p_w   = (const float*)d_in[2];
    const float* p_b   = (const float*)d_in[3];
    const float* Wq    = (const float*)d_in[4];
    const float* Wk    = (const float*)d_in[5];
    const float* Wv    = (const float*)d_in[6];
    const float* Wo    = (const float*)d_in[7];
    const float* ln1_g = (const float*)d_in[8];
    const float* ln1_b = (const float*)d_in[9];
    const float* ln2_g = (const float*)d_in[10];
    const float* ln2_b = (const float*)d_in[11];
    const float* K1    = (const float*)d_in[12];
    const float* c1_b  = (const float*)d_in[13];
    const float* K2    = (const float*)d_in[14];
    const float* c2_b  = (const float*)d_in[15];
    const float* W_out = (const float*)d_in[16];
    const float* b_out = (const float*)d_in[17];
    float* out = (float*)d_out;

    float *state, *prevp, *uw;
    bf16 *xnh, *xnl, *qkvh, *qkvl, *vth, *vtl, *ctxh, *ctxl, *wh, *wl, *hh, *hl;
    bf16 *Wqkvh, *Wqkvl, *Woh, *Wol, *K1h, *K1l, *K2h, *K2l;
    cudaGetSymbolAddress((void**)&state, g_state);
    cudaGetSymbolAddress((void**)&prevp, g_prev);
    cudaGetSymbolAddress((void**)&uw,    g_uw);
    cudaGetSymbolAddress((void**)&xnh,   g_xnh);   cudaGetSymbolAddress((void**)&xnl,  g_xnl);
    cudaGetSymbolAddress((void**)&qkvh,  g_qkvh);  cudaGetSymbolAddress((void**)&qkvl, g_qkvl);
    cudaGetSymbolAddress((void**)&vth,   g_vth);   cudaGetSymbolAddress((void**)&vtl,  g_vtl);
    cudaGetSymbolAddress((void**)&ctxh,  g_ctxh);  cudaGetSymbolAddress((void**)&ctxl, g_ctxl);
    cudaGetSymbolAddress((void**)&wh,    g_wh);    cudaGetSymbolAddress((void**)&wl,   g_wl);
    cudaGetSymbolAddress((void**)&hh,    g_hh);    cudaGetSymbolAddress((void**)&hl,   g_hl);
    cudaGetSymbolAddress((void**)&Wqkvh, g_Wqkvh); cudaGetSymbolAddress((void**)&Wqkvl,g_Wqkvl);
    cudaGetSymbolAddress((void**)&Woh,   g_Woh);   cudaGetSymbolAddress((void**)&Wol,  g_Wol);
    cudaGetSymbolAddress((void**)&K1h,   g_K1h);   cudaGetSymbolAddress((void**)&K1l,  g_K1l);
    cudaGetSymbolAddress((void**)&K2h,   g_K2h);   cudaGetSymbolAddress((void**)&K2l,  g_K2l);

    cudaFuncSetAttribute(mm_gemm<0,0,1>,  cudaFuncAttributeMaxDynamicSharedMemorySize, SMEM_SZ);
    cudaFuncSetAttribute(mm_gemm<0,0,6>,  cudaFuncAttributeMaxDynamicSharedMemorySize, SMEM_SZ);
    cudaFuncSetAttribute(mm_gemm<1,10,2>, cudaFuncAttributeMaxDynamicSharedMemorySize, SMEM_SZ);
    cudaFuncSetAttribute(mm_gemm<1,12,5>, cudaFuncAttributeMaxDynamicSharedMemorySize, SMEM_SZ);
    cudaFuncSetAttribute(attn_fused, cudaFuncAttributeMaxDynamicSharedMemorySize, ASMEM);
    cudaFuncSetAttribute(attn_wv,    cudaFuncAttributeMaxDynamicSharedMemorySize, WSMEM);

    dim3 tb(32, 8);
    prep_square<<<dim3(32, 32, 4), tb>>>(Wq, Wk, Wv, Wo, Wqkvh, Wqkvl, Woh, Wol);
    prep_conv<<<24576, tb>>>(K1, K2, K1h, K1l, K2h, K2l);
    init_sig<<<518, 256>>>();
    embed_init<<<NST_/256, 256>>>(X, emb);

    for (int t = 0; t < NL_; t++) {
        pre_layer<<<ROWS_, 256>>>(t, p_w, p_b, ln1_g, ln1_b);

        // fused QKV: N=3072; V third written transposed into vth/vtl by epilogue
        mm_gemm<0,0,6><<<dim3(24, 32), 256, SMEM_SZ>>>(xnh, xnl, Wqkvh, Wqkvl,
            nullptr, qkvh, qkvl, nullptr, nullptr, nullptr, nullptr, vth, vtl, 3*D_, D_);

        attn_fused<<<dim3(16, 128), 256, ASMEM>>>(qkvh, qkvl, wh, wl);
        attn_wv<<<dim3(4, B_*H_), 256, WSMEM>>>(wh, wl, vth, vtl, ctxh, ctxl);

        dim3 gp(D_/128, ROWS_/128);
        mm_gemm<0,0,1><<<gp, 256, SMEM_SZ>>>(ctxh, ctxl, Woh, Wol,
            state, nullptr, nullptr, state, nullptr, nullptr, nullptr, nullptr, nullptr, D_, D_);
        layernorm_k<<<ROWS_, 256>>>(state, xnh, xnl, ln2_g, ln2_b);

        mm_gemm<1,10,2><<<dim3(F_/128, ROWS_/128), 256, SMEM_SZ>>>(xnh, xnl, K1h, K1l,
            nullptr, hh, hl, nullptr, c1_b, nullptr, nullptr, nullptr, nullptr, F_, 3*D_);
        mm_gemm<1,12,5><<<gp, 256, SMEM_SZ>>>(hh, hl, K2h, K2l,
            state, nullptr, nullptr, state, c2_b, uw, prevp, nullptr, nullptr, D_, 3*F_);
    }

    head_partial<<<dim3(8, 8), 256>>>();
    head_out<<<B_, 256>>>(W_out, b_out, out);
    tail_out<<<ROWS_/256, 256>>>(out);
}